// round 1
// baseline (speedup 1.0000x reference)
#include <cuda_runtime.h>

#define LL 256
#define DD 128
#define HH 4
#define CC 64
#define HC 256
#define NROWS (LL*LL)   // 65536

// ---------------- scratch (static device globals; no allocations) ----------
__device__ __align__(16) float g_x[NROWS*DD];      // layernorm output [s,q,d]
__device__ __align__(16) float g_q[NROWS*HC];      // q proj  [s,h,r,c]
__device__ __align__(16) float g_k[NROWS*HC];      // k proj  [s,h,r,c]
__device__ __align__(16) float g_v[NROWS*HC];      // v proj  [s,h,r,c]
__device__ __align__(16) float g_u[NROWS*HC];      // sigmoid gate [s,h,r,c]
__device__ __align__(16) float g_bias[HH*LL*LL];   // pair_bias + mask bias [h,q,v]
__device__ __align__(16) float g_o[NROWS*HC];      // attention out [s*256+q, h*64+c]

// ---------------- kernel 1: layernorm ----------------
__global__ __launch_bounds__(256) void ln_kernel(const float* __restrict__ in,
                                                 const float* __restrict__ gamma,
                                                 const float* __restrict__ beta) {
    int row  = blockIdx.x * 8 + (threadIdx.x >> 5);
    int lane = threadIdx.x & 31;
    float4 v = reinterpret_cast<const float4*>(in)[(size_t)row * 32 + lane];
    float s  = v.x + v.y + v.z + v.w;
    float ss = v.x*v.x + v.y*v.y + v.z*v.z + v.w*v.w;
#pragma unroll
    for (int o = 16; o; o >>= 1) {
        s  += __shfl_xor_sync(0xffffffffu, s,  o);
        ss += __shfl_xor_sync(0xffffffffu, ss, o);
    }
    float mu  = s * (1.f / 128.f);
    float var = fmaxf(ss * (1.f / 128.f) - mu * mu, 0.f);
    float inv = rsqrtf(var + 1e-5f);
    float4 g = reinterpret_cast<const float4*>(gamma)[lane];
    float4 b = reinterpret_cast<const float4*>(beta)[lane];
    float4 o4;
    o4.x = (v.x - mu) * inv * g.x + b.x;
    o4.y = (v.y - mu) * inv * g.y + b.y;
    o4.z = (v.z - mu) * inv * g.z + b.z;
    o4.w = (v.w - mu) * inv * g.w + b.w;
    reinterpret_cast<float4*>(g_x)[(size_t)row * 32 + lane] = o4;
}

#define FMA16(ACC, A, B) do { \
    ACC[0][0] += A.x*B.x; ACC[0][1] += A.x*B.y; ACC[0][2] += A.x*B.z; ACC[0][3] += A.x*B.w; \
    ACC[1][0] += A.y*B.x; ACC[1][1] += A.y*B.y; ACC[1][2] += A.y*B.z; ACC[1][3] += A.y*B.w; \
    ACC[2][0] += A.z*B.x; ACC[2][1] += A.z*B.y; ACC[2][2] += A.z*B.z; ACC[2][3] += A.z*B.w; \
    ACC[3][0] += A.w*B.x; ACC[3][1] += A.w*B.y; ACC[3][2] += A.w*B.z; ACC[3][3] += A.w*B.w; \
} while (0)

// ---------------- kernel 2: fused QKVU projection GEMM -----------------
// M=65536, N=1024 (q|k|v|u blocks of 256), K=128. 64x64 block tile, 4x4 micro.
__global__ __launch_bounds__(256) void proj_kernel(const float* __restrict__ Wq,
                                                   const float* __restrict__ Wk,
                                                   const float* __restrict__ Wv,
                                                   const float* __restrict__ Wu,
                                                   const float* __restrict__ bu) {
    __shared__ float As[64][68];   // [k][m]
    __shared__ float Bs[64][68];   // [k][n]
    int bm = blockIdx.x, bn = blockIdx.y;
    int jg0 = bn * 64;
    int mat = jg0 >> 8;                  // 0:q 1:k 2:v 3:u (tile never spans matrices)
    const float* W = (mat == 0) ? Wq : (mat == 1) ? Wk : (mat == 2) ? Wv : Wu;
    int ncol0 = jg0 & 255;
    int tid = threadIdx.x;
    int tx = tid & 15, ty = tid >> 4;
    float acc[4][4] = {};
    for (int kt = 0; kt < 2; kt++) {
#pragma unroll
        for (int p = 0; p < 4; p++) {
            int m = ty + p * 16;
            float4 a = *(const float4*)(g_x + ((size_t)(bm * 64 + m)) * 128 + kt * 64 + tx * 4);
            As[tx*4+0][m] = a.x; As[tx*4+1][m] = a.y; As[tx*4+2][m] = a.z; As[tx*4+3][m] = a.w;
            int k = ty + p * 16;
            *(float4*)&Bs[k][tx*4] = *(const float4*)(W + ((size_t)(kt*64 + k)) * HC + ncol0 + tx*4);
        }
        __syncthreads();
#pragma unroll
        for (int k = 0; k < 64; k++) {
            float4 a = *(float4*)&As[k][ty*4];
            float4 b = *(float4*)&Bs[k][tx*4];
            FMA16(acc, a, b);
        }
        __syncthreads();
    }
#pragma unroll
    for (int i = 0; i < 4; i++) {
        int m = bm * 64 + ty * 4 + i;
        int s = m >> 8, r = m & 255;
#pragma unroll
        for (int j = 0; j < 4; j++) {
            int col = ncol0 + tx * 4 + j;
            int h = col >> 6, c = col & 63;
            size_t dst = (((size_t)(s * 4 + h)) * 256 + r) * 64 + c;
            float val = acc[i][j];
            if (mat == 0)      g_q[dst] = val * 0.125f;                     // * C^-0.5
            else if (mat == 1) g_k[dst] = val;
            else if (mat == 2) g_v[dst] = val;
            else               g_u[dst] = 1.f / (1.f + __expf(-(val + bu[col])));
        }
    }
}

// ---------------- kernel 3: pair_bias + mask bias ----------------
__global__ __launch_bounds__(256) void bias_kernel(const float* __restrict__ Wb,
                                                   const float* __restrict__ mask) {
    int pair = blockIdx.x * 8 + (threadIdx.x >> 5);   // q*256+v
    int lane = threadIdx.x & 31;
    float4 xv = reinterpret_cast<const float4*>(g_x)[(size_t)pair * 32 + lane];
    float keep = 0.f;
#pragma unroll
    for (int h = 0; h < 4; h++) {
        int d = lane * 4;
        float s = xv.x * Wb[(d+0)*4 + h] + xv.y * Wb[(d+1)*4 + h]
                + xv.z * Wb[(d+2)*4 + h] + xv.w * Wb[(d+3)*4 + h];
#pragma unroll
        for (int o = 16; o; o >>= 1) s += __shfl_xor_sync(0xffffffffu, s, o);
        if (lane == h) keep = s;
    }
    if (lane < 4) {
        float mb = 1e9f * (mask[pair] - 1.f);
        g_bias[(size_t)lane * 65536 + pair] = keep + mb;
    }
}

// ---------------- kernel 4: attention per (s, h, q-tile of 64) ----------------
#define SPAD 260
#define ATTN_SMEM ((64*68 + 64*SPAD + 64*68 + 64) * 4)
__global__ __launch_bounds__(256) void attn_kernel() {
    extern __shared__ float sm[];
    float (*Kt)[68]   = (float(*)[68])sm;                       // [c][q]
    float (*S)[SPAD]  = (float(*)[SPAD])(sm + 64 * 68);         // [q][v]
    float (*QV)[68]   = (float(*)[68])(sm + 64 * 68 + 64 * SPAD); // Q as [c][v], V as [v][c]
    float* rsum       = sm + 64 * 68 + 64 * SPAD + 64 * 68;

    int b  = blockIdx.x;
    int s  = b >> 4, h = (b >> 2) & 3, qt = b & 3;
    int tid = threadIdx.x;
    int tx = tid & 15, ty = tid >> 4;
    size_t base = ((size_t)(s * 4 + h)) * 256 * 64;

    // K tile transposed into smem
#pragma unroll
    for (int p = 0; p < 4; p++) {
        int r = ty + p * 16;
        float4 a = *(const float4*)(g_k + base + (size_t)(qt * 64 + r) * 64 + tx * 4);
        Kt[tx*4+0][r] = a.x; Kt[tx*4+1][r] = a.y; Kt[tx*4+2][r] = a.z; Kt[tx*4+3][r] = a.w;
    }
    // ---- S = K @ Q^T + bias, over 4 v-tiles ----
    for (int vt = 0; vt < 4; vt++) {
        __syncthreads();
#pragma unroll
        for (int p = 0; p < 4; p++) {
            int r = ty + p * 16;
            float4 a = *(const float4*)(g_q + base + (size_t)(vt * 64 + r) * 64 + tx * 4);
            QV[tx*4+0][r] = a.x; QV[tx*4+1][r] = a.y; QV[tx*4+2][r] = a.z; QV[tx*4+3][r] = a.w;
        }
        __syncthreads();
        float acc[4][4] = {};
#pragma unroll
        for (int c = 0; c < 64; c++) {
            float4 a  = *(float4*)&Kt[c][ty*4];
            float4 b4 = *(float4*)&QV[c][tx*4];
            FMA16(acc, a, b4);
        }
#pragma unroll
        for (int i = 0; i < 4; i++) {
            int qg = qt * 64 + ty * 4 + i;
            const float* brow = g_bias + ((size_t)h * 256 + qg) * 256 + vt * 64 + tx * 4;
            float4 s4;
            s4.x = acc[i][0] + brow[0];
            s4.y = acc[i][1] + brow[1];
            s4.z = acc[i][2] + brow[2];
            s4.w = acc[i][3] + brow[3];
            *(float4*)&S[ty*4 + i][vt * 64 + tx * 4] = s4;
        }
    }
    __syncthreads();
    // ---- softmax over v (4 threads per row) ----
    {
        int row = tid >> 2, part = tid & 3;
        float m = -1e30f;
        for (int v = part * 64; v < part * 64 + 64; v++) m = fmaxf(m, S[row][v]);
        m = fmaxf(m, __shfl_xor_sync(0xffffffffu, m, 1));
        m = fmaxf(m, __shfl_xor_sync(0xffffffffu, m, 2));
        float sum = 0.f;
        for (int v = part * 64; v < part * 64 + 64; v++) {
            float e = __expf(S[row][v] - m);
            S[row][v] = e;
            sum += e;
        }
        sum += __shfl_xor_sync(0xffffffffu, sum, 1);
        sum += __shfl_xor_sync(0xffffffffu, sum, 2);
        if (part == 0) rsum[row] = sum;
    }
    // ---- O = P @ V over 4 v-tiles ----
    float oacc[4][4] = {};
    for (int vt = 0; vt < 4; vt++) {
        __syncthreads();
#pragma unroll
        for (int p = 0; p < 4; p++) {
            int r = ty + p * 16;
            *(float4*)&QV[r][tx*4] = *(const float4*)(g_v + base + (size_t)(vt * 64 + r) * 64 + tx * 4);
        }
        __syncthreads();
#pragma unroll
        for (int vl = 0; vl < 64; vl++) {
            float p0 = S[ty*4+0][vt*64 + vl];
            float p1 = S[ty*4+1][vt*64 + vl];
            float p2 = S[ty*4+2][vt*64 + vl];
            float p3 = S[ty*4+3][vt*64 + vl];
            float4 b4 = *(float4*)&QV[vl][tx*4];
            oacc[0][0] += p0*b4.x; oacc[0][1] += p0*b4.y; oacc[0][2] += p0*b4.z; oacc[0][3] += p0*b4.w;
            oacc[1][0] += p1*b4.x; oacc[1][1] += p1*b4.y; oacc[1][2] += p1*b4.z; oacc[1][3] += p1*b4.w;
            oacc[2][0] += p2*b4.x; oacc[2][1] += p2*b4.y; oacc[2][2] += p2*b4.z; oacc[2][3] += p2*b4.w;
            oacc[3][0] += p3*b4.x; oacc[3][1] += p3*b4.y; oacc[3][2] += p3*b4.z; oacc[3][3] += p3*b4.w;
        }
    }
    // ---- epilogue: /rowsum, * sigmoid gate, store [s*256+q, h*64+c] ----
#pragma unroll
    for (int i = 0; i < 4; i++) {
        int ql = ty * 4 + i;
        int qg = qt * 64 + ql;
        float inv = 1.f / rsum[ql];
        float4 u4 = *(const float4*)(g_u + base + (size_t)qg * 64 + tx * 4);
        float4 o4;
        o4.x = oacc[i][0] * inv * u4.x;
        o4.y = oacc[i][1] * inv * u4.y;
        o4.z = oacc[i][2] * inv * u4.z;
        o4.w = oacc[i][3] * inv * u4.w;
        *(float4*)(g_o + ((size_t)(s * 256 + qg)) * 256 + h * 64 + tx * 4) = o4;
    }
}

// ---------------- kernel 5: output GEMM + bias + mask ----------------
// M=65536, K=256, N=128
__global__ __launch_bounds__(256) void out_kernel(const float* __restrict__ Wo,
                                                  const float* __restrict__ bo,
                                                  const float* __restrict__ mask,
                                                  float* __restrict__ out) {
    __shared__ float As[64][68];
    __shared__ float Bs[64][68];
    int bm = blockIdx.x, bn = blockIdx.y;
    int tid = threadIdx.x, tx = tid & 15, ty = tid >> 4;
    float acc[4][4] = {};
    for (int kt = 0; kt < 4; kt++) {
#pragma unroll
        for (int p = 0; p < 4; p++) {
            int m = ty + p * 16;
            float4 a = *(const float4*)(g_o + ((size_t)(bm * 64 + m)) * 256 + kt * 64 + tx * 4);
            As[tx*4+0][m] = a.x; As[tx*4+1][m] = a.y; As[tx*4+2][m] = a.z; As[tx*4+3][m] = a.w;
            int k = ty + p * 16;
            *(float4*)&Bs[k][tx*4] = *(const float4*)(Wo + ((size_t)(kt*64 + k)) * 128 + bn * 64 + tx * 4);
        }
        __syncthreads();
#pragma unroll
        for (int k = 0; k < 64; k++) {
            float4 a = *(float4*)&As[k][ty*4];
            float4 b = *(float4*)&Bs[k][tx*4];
            FMA16(acc, a, b);
        }
        __syncthreads();
    }
#pragma unroll
    for (int i = 0; i < 4; i++) {
        int m = bm * 64 + ty * 4 + i;
        float mk = mask[m];
        int n0 = bn * 64 + tx * 4;
        float4 o4;
        o4.x = (acc[i][0] + bo[n0 + 0]) * mk;
        o4.y = (acc[i][1] + bo[n0 + 1]) * mk;
        o4.z = (acc[i][2] + bo[n0 + 2]) * mk;
        o4.w = (acc[i][3] + bo[n0 + 3]) * mk;
        *(float4*)(out + (size_t)m * 128 + n0) = o4;
    }
}

// ---------------- launch ----------------
extern "C" void kernel_launch(void* const* d_in, const int* in_sizes, int n_in,
                              void* d_out, int out_size) {
    const float* pair_rep = (const float*)d_in[0];
    const float* mask     = (const float*)d_in[1];
    const float* gamma    = (const float*)d_in[2];
    const float* beta     = (const float*)d_in[3];
    const float* Wq       = (const float*)d_in[4];
    const float* Wk       = (const float*)d_in[5];
    const float* Wv       = (const float*)d_in[6];
    const float* Wb       = (const float*)d_in[7];
    const float* Wu       = (const float*)d_in[8];
    const float* bu       = (const float*)d_in[9];
    const float* Wo       = (const float*)d_in[10];
    const float* bo       = (const float*)d_in[11];
    float* out = (float*)d_out;

    cudaFuncSetAttribute(attn_kernel, cudaFuncAttributeMaxDynamicSharedMemorySize, ATTN_SMEM);

    ln_kernel<<<8192, 256>>>(pair_rep, gamma, beta);
    proj_kernel<<<dim3(1024, 16), 256>>>(Wq, Wk, Wv, Wu, bu);
    bias_kernel<<<8192, 256>>>(Wb, mask);
    attn_kernel<<<4096, 256, ATTN_SMEM>>>();
    out_kernel<<<dim3(1024, 2), 256>>>(Wo, bo, mask, out);
}

// round 2
// speedup vs baseline: 1.2172x; 1.2172x over previous
#include <cuda_runtime.h>

#define LL 256
#define DD 128
#define HH 4
#define CC 64
#define HC 256
#define NROWS (LL*LL)   // 65536

// ---------------- scratch (static device globals; no allocations) ----------
__device__ __align__(16) float g_x[NROWS*DD];      // layernorm output [s,q,d]
__device__ __align__(16) float g_q[NROWS*HC];      // q proj  [s,h,r,c]  (pre-scaled by C^-0.5)
__device__ __align__(16) float g_k[NROWS*HC];      // k proj  [s,h,r,c]
__device__ __align__(16) float g_v[NROWS*HC];      // v proj  [s,h,r,c]
__device__ __align__(16) float g_u[NROWS*HC];      // sigmoid gate [s,h,r,c]
__device__ __align__(16) float g_bias[HH*LL*LL];   // pair_bias + mask bias [h,q,v]
__device__ __align__(16) float g_o[NROWS*HC];      // attention out [s*256+q, h*64+c]

// ---------------- kernel 1: layernorm ----------------
__global__ __launch_bounds__(256) void ln_kernel(const float* __restrict__ in,
                                                 const float* __restrict__ gamma,
                                                 const float* __restrict__ beta) {
    int row  = blockIdx.x * 8 + (threadIdx.x >> 5);
    int lane = threadIdx.x & 31;
    float4 v = reinterpret_cast<const float4*>(in)[(size_t)row * 32 + lane];
    float s  = v.x + v.y + v.z + v.w;
    float ss = v.x*v.x + v.y*v.y + v.z*v.z + v.w*v.w;
#pragma unroll
    for (int o = 16; o; o >>= 1) {
        s  += __shfl_xor_sync(0xffffffffu, s,  o);
        ss += __shfl_xor_sync(0xffffffffu, ss, o);
    }
    float mu  = s * (1.f / 128.f);
    float var = fmaxf(ss * (1.f / 128.f) - mu * mu, 0.f);
    float inv = rsqrtf(var + 1e-5f);
    float4 g = reinterpret_cast<const float4*>(gamma)[lane];
    float4 b = reinterpret_cast<const float4*>(beta)[lane];
    float4 o4;
    o4.x = (v.x - mu) * inv * g.x + b.x;
    o4.y = (v.y - mu) * inv * g.y + b.y;
    o4.z = (v.z - mu) * inv * g.z + b.z;
    o4.w = (v.w - mu) * inv * g.w + b.w;
    reinterpret_cast<float4*>(g_x)[(size_t)row * 32 + lane] = o4;
}

// ---------------- kernel 2: fused QKVU projection GEMM -----------------
// M=65536, N=1024 (q|k|v|u blocks of 256), K=128. 128x128 tile, 8x8 micro.
__global__ __launch_bounds__(256) void proj_kernel(const float* __restrict__ Wq,
                                                   const float* __restrict__ Wk,
                                                   const float* __restrict__ Wv,
                                                   const float* __restrict__ Wu,
                                                   const float* __restrict__ bu) {
    __shared__ float As[16][132];   // [k][m]
    __shared__ float Bs[16][132];   // [k][n]
    int bm = blockIdx.x;            // 512 m-tiles
    int bn = blockIdx.y;            // 8 n-tiles of 128
    int mat = bn >> 1;              // 0:q 1:k 2:v 3:u
    int ncol0 = (bn & 1) * 128;
    const float* W = (mat == 0) ? Wq : (mat == 1) ? Wk : (mat == 2) ? Wv : Wu;
    int tid = threadIdx.x;
    int tx = tid & 15, ty = tid >> 4;
    float acc[8][8] = {};
    for (int kt = 0; kt < 8; kt++) {
        __syncthreads();
#pragma unroll
        for (int t = 0; t < 2; t++) {
            int idx = tid + 256 * t;
            int m = idx >> 2, kq = idx & 3;
            float4 a = *(const float4*)(g_x + ((size_t)(bm * 128 + m)) * 128 + kt * 16 + kq * 4);
            As[kq*4+0][m] = a.x; As[kq*4+1][m] = a.y; As[kq*4+2][m] = a.z; As[kq*4+3][m] = a.w;
            int k = idx >> 5, nq = idx & 31;
            *(float4*)&Bs[k][nq*4] = *(const float4*)(W + (size_t)(kt*16 + k) * HC + ncol0 + nq*4);
        }
        __syncthreads();
#pragma unroll
        for (int k = 0; k < 16; k++) {
            float4 a0 = *(float4*)&As[k][ty*8];
            float4 a1 = *(float4*)&As[k][ty*8+4];
            float4 b0 = *(float4*)&Bs[k][tx*8];
            float4 b1 = *(float4*)&Bs[k][tx*8+4];
            float av[8] = {a0.x,a0.y,a0.z,a0.w,a1.x,a1.y,a1.z,a1.w};
            float bv[8] = {b0.x,b0.y,b0.z,b0.w,b1.x,b1.y,b1.z,b1.w};
#pragma unroll
            for (int i = 0; i < 8; i++)
#pragma unroll
                for (int j = 0; j < 8; j++)
                    acc[i][j] += av[i] * bv[j];
        }
    }
#pragma unroll
    for (int i = 0; i < 8; i++) {
        int m = bm * 128 + ty * 8 + i;
        int s = m >> 8, rr = m & 255;
#pragma unroll
        for (int jj = 0; jj < 2; jj++) {
            int col = ncol0 + tx * 8 + jj * 4;
            int h = col >> 6, c = col & 63;
            size_t dst = (((size_t)(s * 4 + h)) * 256 + rr) * 64 + c;
            float4 o4 = make_float4(acc[i][jj*4+0], acc[i][jj*4+1], acc[i][jj*4+2], acc[i][jj*4+3]);
            if (mat == 0) {
                o4.x *= 0.125f; o4.y *= 0.125f; o4.z *= 0.125f; o4.w *= 0.125f;
                *(float4*)(g_q + dst) = o4;
            } else if (mat == 1) {
                *(float4*)(g_k + dst) = o4;
            } else if (mat == 2) {
                *(float4*)(g_v + dst) = o4;
            } else {
                float4 b = *(const float4*)(bu + col);
                o4.x = 1.f / (1.f + __expf(-(o4.x + b.x)));
                o4.y = 1.f / (1.f + __expf(-(o4.y + b.y)));
                o4.z = 1.f / (1.f + __expf(-(o4.z + b.z)));
                o4.w = 1.f / (1.f + __expf(-(o4.w + b.w)));
                *(float4*)(g_u + dst) = o4;
            }
        }
    }
}

// ---------------- kernel 3: pair_bias + mask bias ----------------
__global__ __launch_bounds__(256) void bias_kernel(const float* __restrict__ Wb,
                                                   const float* __restrict__ mask) {
    int pair = blockIdx.x * 8 + (threadIdx.x >> 5);   // q*256+v
    int lane = threadIdx.x & 31;
    float4 xv = reinterpret_cast<const float4*>(g_x)[(size_t)pair * 32 + lane];
    float keep = 0.f;
#pragma unroll
    for (int h = 0; h < 4; h++) {
        int d = lane * 4;
        float s = xv.x * Wb[(d+0)*4 + h] + xv.y * Wb[(d+1)*4 + h]
                + xv.z * Wb[(d+2)*4 + h] + xv.w * Wb[(d+3)*4 + h];
#pragma unroll
        for (int o = 16; o; o >>= 1) s += __shfl_xor_sync(0xffffffffu, s, o);
        if (lane == h) keep = s;
    }
    if (lane < 4) {
        float mb = 1e9f * (mask[pair] - 1.f);
        g_bias[(size_t)lane * 65536 + pair] = keep + mb;
    }
}

// ---------------- kernel 4: attention per (s, h, q-tile of 64) ----------------
// smem layout (floats): S[64][260] | Kt[64][68] | Buf(QT[16][260] / Vs[64][68]) | pm[256] ps[256] rinv[64]
#define ATTN_SMEM ((16640 + 4352 + 4352 + 576) * 4)
__global__ __launch_bounds__(256) void attn_kernel() {
    extern __shared__ float sm[];
    float (*S)[260]  = (float(*)[260])sm;
    float (*Kt)[68]  = (float(*)[68])(sm + 16640);
    float (*Buf)[260]= (float(*)[260])(sm + 20992);
    float (*Vs)[68]  = (float(*)[68])(sm + 20992);
    float* pm   = sm + 25344;
    float* ps   = pm + 256;
    float* rinv = ps + 256;

    int b  = blockIdx.x;
    int s  = b >> 4, h = (b >> 2) & 3, qt = b & 3;
    int tid = threadIdx.x;
    size_t base = ((size_t)(s * 4 + h)) * 256 * 64;

    // K tile transposed into smem: Kt[c][q]
#pragma unroll
    for (int t = 0; t < 4; t++) {
        int idx = tid + 256 * t;
        int r = idx >> 4, cq = idx & 15;
        float4 a = *(const float4*)(g_k + base + (size_t)(qt * 64 + r) * 64 + cq * 4);
        Kt[cq*4+0][r] = a.x; Kt[cq*4+1][r] = a.y; Kt[cq*4+2][r] = a.z; Kt[cq*4+3][r] = a.w;
    }

    // ---- S[q][v] = sum_c K[q][c]*Q[v][c], 8x8 micro over 64x256 ----
    int tx = tid & 31, ty = tid >> 5;   // tx: v octet (0..31), ty: q octet (0..7)
    float acc[8][8] = {};
    for (int ct = 0; ct < 4; ct++) {
        __syncthreads();
#pragma unroll
        for (int t = 0; t < 4; t++) {
            int idx = tid + 256 * t;
            int v = idx >> 2, cq = idx & 3;
            float4 a = *(const float4*)(g_q + base + (size_t)v * 64 + ct * 16 + cq * 4);
            Buf[cq*4+0][v] = a.x; Buf[cq*4+1][v] = a.y; Buf[cq*4+2][v] = a.z; Buf[cq*4+3][v] = a.w;
        }
        __syncthreads();
#pragma unroll
        for (int cc = 0; cc < 16; cc++) {
            int c = ct * 16 + cc;
            float4 a0 = *(float4*)&Kt[c][ty*8];
            float4 a1 = *(float4*)&Kt[c][ty*8+4];
            float4 b0 = *(float4*)&Buf[cc][tx*8];
            float4 b1 = *(float4*)&Buf[cc][tx*8+4];
            float av[8] = {a0.x,a0.y,a0.z,a0.w,a1.x,a1.y,a1.z,a1.w};
            float bv[8] = {b0.x,b0.y,b0.z,b0.w,b1.x,b1.y,b1.z,b1.w};
#pragma unroll
            for (int i = 0; i < 8; i++)
#pragma unroll
                for (int j = 0; j < 8; j++)
                    acc[i][j] += av[i] * bv[j];
        }
    }

    // ---- add bias, write S[q][v] ----
    int qg0 = qt * 64 + ty * 8;
#pragma unroll
    for (int i = 0; i < 8; i++) {
        const float4* bp = (const float4*)(g_bias + ((size_t)h * 256 + qg0 + i) * 256) + tx * 2;
        float4 b0 = bp[0], b1 = bp[1];
        acc[i][0] += b0.x; acc[i][1] += b0.y; acc[i][2] += b0.z; acc[i][3] += b0.w;
        acc[i][4] += b1.x; acc[i][5] += b1.y; acc[i][6] += b1.z; acc[i][7] += b1.w;
        *(float4*)&S[ty*8+i][tx*8]   = make_float4(acc[i][0], acc[i][1], acc[i][2], acc[i][3]);
        *(float4*)&S[ty*8+i][tx*8+4] = make_float4(acc[i][4], acc[i][5], acc[i][6], acc[i][7]);
    }
    __syncthreads();

    // ---- softmax over v: 4 threads per q-row, float4 row scans ----
    {
        int q = tid & 63, p = tid >> 6;
        float4* Srow = (float4*)&S[q][0];
        float m = -3e38f;
#pragma unroll
        for (int k = 0; k < 16; k++) {
            float4 x = Srow[p*16 + k];
            m = fmaxf(m, fmaxf(fmaxf(x.x, x.y), fmaxf(x.z, x.w)));
        }
        pm[p*64 + q] = m;
        __syncthreads();
        m = fmaxf(fmaxf(pm[q], pm[64+q]), fmaxf(pm[128+q], pm[192+q]));
        float sum = 0.f;
#pragma unroll
        for (int k = 0; k < 16; k++) {
            float4 x = Srow[p*16 + k];
            x.x = __expf(x.x - m); x.y = __expf(x.y - m);
            x.z = __expf(x.z - m); x.w = __expf(x.w - m);
            sum += x.x + x.y + x.z + x.w;
            Srow[p*16 + k] = x;
        }
        ps[p*64 + q] = sum;
        __syncthreads();
        if (p == 0) rinv[q] = 1.f / (ps[q] + ps[64+q] + ps[128+q] + ps[192+q]);
    }
    __syncthreads();

    // ---- O[q][c] = sum_v P[q][v]*V[v][c], 4x4 micro over 64x64 ----
    int cx = tid & 15, qy = tid >> 4;
    float oacc[4][4] = {};
    for (int vt = 0; vt < 4; vt++) {
        __syncthreads();
#pragma unroll
        for (int t = 0; t < 4; t++) {
            int idx = tid + 256 * t;
            int r = idx >> 4, cq = idx & 15;
            *(float4*)&Vs[r][cq*4] = *(const float4*)(g_v + base + (size_t)(vt * 64 + r) * 64 + cq * 4);
        }
        __syncthreads();
#pragma unroll 8
        for (int vv = 0; vv < 64; vv++) {
            int v = vt * 64 + vv;
            float p0 = S[qy*4+0][v];
            float p1 = S[qy*4+1][v];
            float p2 = S[qy*4+2][v];
            float p3 = S[qy*4+3][v];
            float4 b4 = *(float4*)&Vs[vv][cx*4];
            oacc[0][0] += p0*b4.x; oacc[0][1] += p0*b4.y; oacc[0][2] += p0*b4.z; oacc[0][3] += p0*b4.w;
            oacc[1][0] += p1*b4.x; oacc[1][1] += p1*b4.y; oacc[1][2] += p1*b4.z; oacc[1][3] += p1*b4.w;
            oacc[2][0] += p2*b4.x; oacc[2][1] += p2*b4.y; oacc[2][2] += p2*b4.z; oacc[2][3] += p2*b4.w;
            oacc[3][0] += p3*b4.x; oacc[3][1] += p3*b4.y; oacc[3][2] += p3*b4.z; oacc[3][3] += p3*b4.w;
        }
    }

    // ---- epilogue: /rowsum, * sigmoid gate, store [s*256+q, h*64+c] ----
#pragma unroll
    for (int i = 0; i < 4; i++) {
        int ql = qy * 4 + i;
        int qg = qt * 64 + ql;
        float rv = rinv[ql];
        float4 u4 = *(const float4*)(g_u + base + (size_t)qg * 64 + cx * 4);
        float4 o4;
        o4.x = oacc[i][0] * rv * u4.x;
        o4.y = oacc[i][1] * rv * u4.y;
        o4.z = oacc[i][2] * rv * u4.z;
        o4.w = oacc[i][3] * rv * u4.w;
        *(float4*)(g_o + ((size_t)(s * 256 + qg)) * 256 + h * 64 + cx * 4) = o4;
    }
}

// ---------------- kernel 5: output GEMM + bias + mask ----------------
// M=65536, K=256, N=128. 128x128 tile, 8x8 micro.
__global__ __launch_bounds__(256) void out_kernel(const float* __restrict__ Wo,
                                                  const float* __restrict__ bo,
                                                  const float* __restrict__ mask,
                                                  float* __restrict__ out) {
    __shared__ float As[16][132];
    __shared__ float Bs[16][132];
    int bm = blockIdx.x;
    int tid = threadIdx.x, tx = tid & 15, ty = tid >> 4;
    float acc[8][8] = {};
    for (int kt = 0; kt < 16; kt++) {
        __syncthreads();
#pragma unroll
        for (int t = 0; t < 2; t++) {
            int idx = tid + 256 * t;
            int m = idx >> 2, kq = idx & 3;
            float4 a = *(const float4*)(g_o + ((size_t)(bm * 128 + m)) * 256 + kt * 16 + kq * 4);
            As[kq*4+0][m] = a.x; As[kq*4+1][m] = a.y; As[kq*4+2][m] = a.z; As[kq*4+3][m] = a.w;
            int k = idx >> 5, nq = idx & 31;
            *(float4*)&Bs[k][nq*4] = *(const float4*)(Wo + (size_t)(kt*16 + k) * 128 + nq*4);
        }
        __syncthreads();
#pragma unroll
        for (int k = 0; k < 16; k++) {
            float4 a0 = *(float4*)&As[k][ty*8];
            float4 a1 = *(float4*)&As[k][ty*8+4];
            float4 b0 = *(float4*)&Bs[k][tx*8];
            float4 b1 = *(float4*)&Bs[k][tx*8+4];
            float av[8] = {a0.x,a0.y,a0.z,a0.w,a1.x,a1.y,a1.z,a1.w};
            float bv[8] = {b0.x,b0.y,b0.z,b0.w,b1.x,b1.y,b1.z,b1.w};
#pragma unroll
            for (int i = 0; i < 8; i++)
#pragma unroll
                for (int j = 0; j < 8; j++)
                    acc[i][j] += av[i] * bv[j];
        }
    }
#pragma unroll
    for (int i = 0; i < 8; i++) {
        int m = bm * 128 + ty * 8 + i;
        float mk = mask[m];
#pragma unroll
        for (int jj = 0; jj < 2; jj++) {
            int n0 = tx * 8 + jj * 4;
            float4 b = *(const float4*)(bo + n0);
            float4 o4;
            o4.x = (acc[i][jj*4+0] + b.x) * mk;
            o4.y = (acc[i][jj*4+1] + b.y) * mk;
            o4.z = (acc[i][jj*4+2] + b.z) * mk;
            o4.w = (acc[i][jj*4+3] + b.w) * mk;
            *(float4*)(out + (size_t)m * 128 + n0) = o4;
        }
    }
}

// ---------------- launch ----------------
extern "C" void kernel_launch(void* const* d_in, const int* in_sizes, int n_in,
                              void* d_out, int out_size) {
    const float* pair_rep = (const float*)d_in[0];
    const float* mask     = (const float*)d_in[1];
    const float* gamma    = (const float*)d_in[2];
    const float* beta     = (const float*)d_in[3];
    const float* Wq       = (const float*)d_in[4];
    const float* Wk       = (const float*)d_in[5];
    const float* Wv       = (const float*)d_in[6];
    const float* Wb       = (const float*)d_in[7];
    const float* Wu       = (const float*)d_in[8];
    const float* bu       = (const float*)d_in[9];
    const float* Wo       = (const float*)d_in[10];
    const float* bo       = (const float*)d_in[11];
    float* out = (float*)d_out;

    cudaFuncSetAttribute(attn_kernel, cudaFuncAttributeMaxDynamicSharedMemorySize, ATTN_SMEM);

    ln_kernel<<<8192, 256>>>(pair_rep, gamma, beta);
    proj_kernel<<<dim3(512, 8), 256>>>(Wq, Wk, Wv, Wu, bu);
    bias_kernel<<<8192, 256>>>(Wb, mask);
    attn_kernel<<<4096, 256, ATTN_SMEM>>>();
    out_kernel<<<512, 256>>>(Wo, bo, mask, out);
}

// round 3
// speedup vs baseline: 1.4106x; 1.1589x over previous
#include <cuda_runtime.h>
#include <cstdint>

#define LL 256
#define HC 256
#define NROWS (LL*LL)   // 65536

// ---------------- scratch (static device globals; no allocations) ----------
__device__ __align__(16) float g_x[NROWS*128];     // layernorm output [s,q,d]
__device__ __align__(16) float g_q[NROWS*HC];      // q proj  [s,h,r,c]  (pre-scaled by C^-0.5)
__device__ __align__(16) float g_k[NROWS*HC];      // k proj  [s,h,r,c]
__device__ __align__(16) float g_v[NROWS*HC];      // v proj  [s,h,r,c]
__device__ __align__(16) float g_u[NROWS*HC];      // sigmoid gate [s,h,r,c]
__device__ __align__(16) float g_bias[4*NROWS];    // pair_bias + mask bias [h,q,v]
__device__ __align__(16) float g_o[NROWS*HC];      // attention out [s*256+q, h*64+c]

// ---------------- tf32 mma helpers ----------------
__device__ __forceinline__ uint32_t cvt_tf32(float x) {
    uint32_t u; asm("cvt.rna.tf32.f32 %0, %1;" : "=r"(u) : "f"(x)); return u;
}
__device__ __forceinline__ void split_tf32(float x, uint32_t& hi, uint32_t& lo) {
    hi = cvt_tf32(x);
    lo = cvt_tf32(x - __uint_as_float(hi));
}
// D += A(16x8, row) * B(8x8, col)
__device__ __forceinline__ void mma_tf32(float* c, const uint32_t* a, const uint32_t* b) {
    asm volatile("mma.sync.aligned.m16n8k8.row.col.f32.tf32.tf32.f32 "
        "{%0,%1,%2,%3},{%4,%5,%6,%7},{%8,%9},{%0,%1,%2,%3};"
        : "+f"(c[0]), "+f"(c[1]), "+f"(c[2]), "+f"(c[3])
        : "r"(a[0]), "r"(a[1]), "r"(a[2]), "r"(a[3]), "r"(b[0]), "r"(b[1]));
}

// ---------------- kernel 1: layernorm ----------------
__global__ __launch_bounds__(256) void ln_kernel(const float* __restrict__ in,
                                                 const float* __restrict__ gamma,
                                                 const float* __restrict__ beta) {
    int row  = blockIdx.x * 8 + (threadIdx.x >> 5);
    int lane = threadIdx.x & 31;
    float4 v = reinterpret_cast<const float4*>(in)[(size_t)row * 32 + lane];
    float s  = v.x + v.y + v.z + v.w;
    float ss = v.x*v.x + v.y*v.y + v.z*v.z + v.w*v.w;
#pragma unroll
    for (int o = 16; o; o >>= 1) {
        s  += __shfl_xor_sync(0xffffffffu, s,  o);
        ss += __shfl_xor_sync(0xffffffffu, ss, o);
    }
    float mu  = s * (1.f / 128.f);
    float var = fmaxf(ss * (1.f / 128.f) - mu * mu, 0.f);
    float inv = rsqrtf(var + 1e-5f);
    float4 g = reinterpret_cast<const float4*>(gamma)[lane];
    float4 b = reinterpret_cast<const float4*>(beta)[lane];
    float4 o4;
    o4.x = (v.x - mu) * inv * g.x + b.x;
    o4.y = (v.y - mu) * inv * g.y + b.y;
    o4.z = (v.z - mu) * inv * g.z + b.z;
    o4.w = (v.w - mu) * inv * g.w + b.w;
    reinterpret_cast<float4*>(g_x)[(size_t)row * 32 + lane] = o4;
}

// ---------------- kernel 2: projection GEMM (tf32 mma) -----------------
// M=65536, N=512 per instantiation (two matrices of 256), K=128.
// CTA tile 128x128, 8 warps, warp tile 32x64.
template<int MATBASE, bool SPLIT>
__global__ __launch_bounds__(256) void proj_kernel(const float* __restrict__ W0,
                                                   const float* __restrict__ W1,
                                                   const float* __restrict__ bu) {
    __shared__ float As[128][36];   // [m][k], stride%32==4 -> conflict-free frag reads
    __shared__ float Bs[32][136];   // [k][n], stride%32==8 -> conflict-free frag reads
    int bm = blockIdx.x;            // 512
    int bn = blockIdx.y;            // 0..3
    int mat = MATBASE + (bn >> 1);
    const float* W = (bn >> 1) ? W1 : W0;
    int ncol0 = (bn & 1) * 128;
    int tid = threadIdx.x, lane = tid & 31, warp = tid >> 5;
    int g = lane >> 2, tig = lane & 3;
    int wm = (warp & 3) * 32, wn = (warp >> 2) * 64;
    float c[2][8][4] = {};
    for (int kt = 0; kt < 4; kt++) {
        __syncthreads();
#pragma unroll
        for (int t = 0; t < 4; t++) {
            int idx = tid + 256 * t;
            int m = idx >> 3, kq = idx & 7;
            *(float4*)&As[m][kq*4] = *(const float4*)(g_x + (size_t)(bm*128+m)*128 + kt*32 + kq*4);
            int k = idx >> 5, nq = idx & 31;
            *(float4*)&Bs[k][nq*4] = *(const float4*)(W + (size_t)(kt*32+k)*HC + ncol0 + nq*4);
        }
        __syncthreads();
#pragma unroll
        for (int k8 = 0; k8 < 4; k8++) {
            int k0 = k8 * 8;
            uint32_t ah[2][4], al[2][4];
#pragma unroll
            for (int mi = 0; mi < 2; mi++) {
                float x0 = As[wm+mi*16+g  ][k0+tig];
                float x1 = As[wm+mi*16+g+8][k0+tig];
                float x2 = As[wm+mi*16+g  ][k0+tig+4];
                float x3 = As[wm+mi*16+g+8][k0+tig+4];
                if (SPLIT) {
                    split_tf32(x0, ah[mi][0], al[mi][0]);
                    split_tf32(x1, ah[mi][1], al[mi][1]);
                    split_tf32(x2, ah[mi][2], al[mi][2]);
                    split_tf32(x3, ah[mi][3], al[mi][3]);
                } else {
                    ah[mi][0] = cvt_tf32(x0); ah[mi][1] = cvt_tf32(x1);
                    ah[mi][2] = cvt_tf32(x2); ah[mi][3] = cvt_tf32(x3);
                }
            }
#pragma unroll
            for (int ni = 0; ni < 8; ni++) {
                float y0 = Bs[k0+tig  ][wn+ni*8+g];
                float y1 = Bs[k0+tig+4][wn+ni*8+g];
                uint32_t bh[2], bl[2];
                if (SPLIT) { split_tf32(y0, bh[0], bl[0]); split_tf32(y1, bh[1], bl[1]); }
                else       { bh[0] = cvt_tf32(y0); bh[1] = cvt_tf32(y1); }
#pragma unroll
                for (int mi = 0; mi < 2; mi++) {
                    mma_tf32(c[mi][ni], ah[mi], bh);
                    if (SPLIT) {
                        mma_tf32(c[mi][ni], al[mi], bh);
                        mma_tf32(c[mi][ni], ah[mi], bl);
                    }
                }
            }
        }
    }
    // epilogue: scatter to [s,h,r,c] layout
#pragma unroll
    for (int mi = 0; mi < 2; mi++) {
#pragma unroll
        for (int rsel = 0; rsel < 2; rsel++) {
            int m = bm * 128 + wm + mi * 16 + g + rsel * 8;
            int s = m >> 8, rr = m & 255;
#pragma unroll
            for (int ni = 0; ni < 8; ni++) {
                int col = ncol0 + wn + ni * 8 + tig * 2;
                float v0 = c[mi][ni][rsel*2+0];
                float v1 = c[mi][ni][rsel*2+1];
                int h = col >> 6, cc = col & 63;
                size_t dst = (((size_t)(s*4+h))*256 + rr)*64 + cc;
                float2 o2;
                if (mat == 0) {
                    o2 = make_float2(v0 * 0.125f, v1 * 0.125f);
                    *(float2*)(g_q + dst) = o2;
                } else if (mat == 1) {
                    *(float2*)(g_k + dst) = make_float2(v0, v1);
                } else if (mat == 2) {
                    *(float2*)(g_v + dst) = make_float2(v0, v1);
                } else {
                    float2 b2 = *(const float2*)(bu + col);
                    o2.x = 1.f / (1.f + __expf(-(v0 + b2.x)));
                    o2.y = 1.f / (1.f + __expf(-(v1 + b2.y)));
                    *(float2*)(g_u + dst) = o2;
                }
            }
        }
    }
}

// ---------------- kernel 3: pair_bias + mask bias ----------------
__global__ __launch_bounds__(256) void bias_kernel(const float* __restrict__ Wb,
                                                   const float* __restrict__ mask) {
    int pair = blockIdx.x * 8 + (threadIdx.x >> 5);   // q*256+v
    int lane = threadIdx.x & 31;
    float4 xv = reinterpret_cast<const float4*>(g_x)[(size_t)pair * 32 + lane];
    float keep = 0.f;
#pragma unroll
    for (int h = 0; h < 4; h++) {
        int d = lane * 4;
        float s = xv.x * Wb[(d+0)*4 + h] + xv.y * Wb[(d+1)*4 + h]
                + xv.z * Wb[(d+2)*4 + h] + xv.w * Wb[(d+3)*4 + h];
#pragma unroll
        for (int o = 16; o; o >>= 1) s += __shfl_xor_sync(0xffffffffu, s, o);
        if (lane == h) keep = s;
    }
    if (lane < 4) {
        float mb = 1e9f * (mask[pair] - 1.f);
        g_bias[(size_t)lane * 65536 + pair] = keep + mb;
    }
}

// ---------------- kernel 4: attention per (s, h, q-tile of 64), tf32 mma -----
#define SS 260
#define ATTN_SMEM ((64*SS + 64*68 + 256*68 + 64) * 4)
__global__ __launch_bounds__(512) void attn_kernel() {
    extern __shared__ float sm[];
    float (*S)[SS]  = (float(*)[SS])sm;                        // [q][v] 64x260
    float (*Ks)[68] = (float(*)[68])(sm + 64*SS);              // [q][c] 64x68
    float (*QV)[68] = (float(*)[68])(sm + 64*SS + 64*68);      // Q then V: [v][c] 256x68
    float* rinv     = sm + 64*SS + 64*68 + 256*68;

    int b  = blockIdx.x;
    int s  = b >> 4, h = (b >> 2) & 3, qt = b & 3;
    int tid = threadIdx.x, lane = tid & 31, warp = tid >> 5;
    int g = lane >> 2, tig = lane & 3;
    size_t base = ((size_t)(s*4+h)) * 256 * 64;

    // load K tile (64x64) and full Q (256x64)
#pragma unroll
    for (int t = 0; t < 2; t++) {
        int idx = tid + 512 * t;
        int r = idx >> 4, cq = idx & 15;
        *(float4*)&Ks[r][cq*4] = *(const float4*)(g_k + base + (size_t)(qt*64+r)*64 + cq*4);
    }
#pragma unroll
    for (int t = 0; t < 8; t++) {
        int idx = tid + 512 * t;
        int v = idx >> 4, cq = idx & 15;
        *(float4*)&QV[v][cq*4] = *(const float4*)(g_q + base + (size_t)v*64 + cq*4);
    }
    __syncthreads();

    // ---- S = K @ Q^T (split tf32): warp tile 16(q) x 64(v) ----
    {
        int q0 = (warp & 3) * 16, v0 = (warp >> 2) * 64;
        float c[8][4] = {};
#pragma unroll
        for (int k8 = 0; k8 < 8; k8++) {
            int k0 = k8 * 8;
            uint32_t ah[4], al[4];
            split_tf32(Ks[q0+g  ][k0+tig  ], ah[0], al[0]);
            split_tf32(Ks[q0+g+8][k0+tig  ], ah[1], al[1]);
            split_tf32(Ks[q0+g  ][k0+tig+4], ah[2], al[2]);
            split_tf32(Ks[q0+g+8][k0+tig+4], ah[3], al[3]);
#pragma unroll
            for (int ni = 0; ni < 8; ni++) {
                uint32_t bh[2], bl[2];
                split_tf32(QV[v0+ni*8+g][k0+tig  ], bh[0], bl[0]);
                split_tf32(QV[v0+ni*8+g][k0+tig+4], bh[1], bl[1]);
                mma_tf32(c[ni], ah, bh);
                mma_tf32(c[ni], al, bh);
                mma_tf32(c[ni], ah, bl);
            }
        }
#pragma unroll
        for (int ni = 0; ni < 8; ni++) {
            *(float2*)&S[q0+g  ][v0+ni*8+tig*2] = make_float2(c[ni][0], c[ni][1]);
            *(float2*)&S[q0+g+8][v0+ni*8+tig*2] = make_float2(c[ni][2], c[ni][3]);
        }
    }
    __syncthreads();

    // load V into QV buffer (Q no longer needed)
#pragma unroll
    for (int t = 0; t < 8; t++) {
        int idx = tid + 512 * t;
        int v = idx >> 4, cq = idx & 15;
        *(float4*)&QV[v][cq*4] = *(const float4*)(g_v + base + (size_t)v*64 + cq*4);
    }

    // ---- softmax over v with fused bias add: 8 threads per q row ----
    {
        int q = tid >> 3, p = tid & 7;
        const float4* bp = (const float4*)(g_bias + ((size_t)h*256 + qt*64 + q)*256) + p*8;
        float4* Srow = (float4*)&S[q][0] + p*8;
        float xs[32];
        float m = -3e38f;
#pragma unroll
        for (int kk = 0; kk < 8; kk++) {
            float4 x = Srow[kk];
            float4 bb = bp[kk];
            xs[kk*4+0] = x.x + bb.x; xs[kk*4+1] = x.y + bb.y;
            xs[kk*4+2] = x.z + bb.z; xs[kk*4+3] = x.w + bb.w;
#pragma unroll
            for (int j = 0; j < 4; j++) m = fmaxf(m, xs[kk*4+j]);
        }
        m = fmaxf(m, __shfl_xor_sync(0xffffffffu, m, 1));
        m = fmaxf(m, __shfl_xor_sync(0xffffffffu, m, 2));
        m = fmaxf(m, __shfl_xor_sync(0xffffffffu, m, 4));
        float sum = 0.f;
#pragma unroll
        for (int kk = 0; kk < 8; kk++) {
            float4 e;
            e.x = __expf(xs[kk*4+0] - m); e.y = __expf(xs[kk*4+1] - m);
            e.z = __expf(xs[kk*4+2] - m); e.w = __expf(xs[kk*4+3] - m);
            sum += e.x + e.y + e.z + e.w;
            Srow[kk] = e;
        }
        sum += __shfl_xor_sync(0xffffffffu, sum, 1);
        sum += __shfl_xor_sync(0xffffffffu, sum, 2);
        sum += __shfl_xor_sync(0xffffffffu, sum, 4);
        if (p == 0) rinv[q] = 1.f / sum;
    }
    __syncthreads();

    // ---- O = P @ V (single tf32): warp tile 16(q) x 16(c) ----
    {
        int q0 = (warp & 3) * 16, c0 = (warp >> 2) * 16;
        float oc[2][4] = {};
#pragma unroll
        for (int k8 = 0; k8 < 32; k8++) {
            int k0 = k8 * 8;
            uint32_t a[4];
            a[0] = cvt_tf32(S[q0+g  ][k0+tig  ]);
            a[1] = cvt_tf32(S[q0+g+8][k0+tig  ]);
            a[2] = cvt_tf32(S[q0+g  ][k0+tig+4]);
            a[3] = cvt_tf32(S[q0+g+8][k0+tig+4]);
#pragma unroll
            for (int ni = 0; ni < 2; ni++) {
                uint32_t bb[2];
                bb[0] = cvt_tf32(QV[k0+tig  ][c0+ni*8+g]);
                bb[1] = cvt_tf32(QV[k0+tig+4][c0+ni*8+g]);
                mma_tf32(oc[ni], a, bb);
            }
        }
        // epilogue: /rowsum, * sigmoid gate, store to g_o [s*256+q][h*64+c]
#pragma unroll
        for (int ni = 0; ni < 2; ni++) {
#pragma unroll
            for (int rsel = 0; rsel < 2; rsel++) {
                int ql = q0 + g + rsel * 8;
                int qg = qt * 64 + ql;
                int cc = c0 + ni * 8 + tig * 2;
                float rv = rinv[ql];
                float2 u2 = *(const float2*)(g_u + base + (size_t)qg*64 + cc);
                float2 o2;
                o2.x = oc[ni][rsel*2+0] * rv * u2.x;
                o2.y = oc[ni][rsel*2+1] * rv * u2.y;
                *(float2*)(g_o + ((size_t)(s*256+qg))*256 + h*64 + cc) = o2;
            }
        }
    }
}

// ---------------- kernel 5: output GEMM (tf32 mma) ----------------
// M=65536, K=256, N=128. CTA tile 128x128, warp tile 32x64.
__global__ __launch_bounds__(256) void out_kernel(const float* __restrict__ Wo,
                                                  const float* __restrict__ bo,
                                                  const float* __restrict__ mask,
                                                  float* __restrict__ out) {
    __shared__ float As[128][36];
    __shared__ float Bs[32][136];
    int bm = blockIdx.x;
    int tid = threadIdx.x, lane = tid & 31, warp = tid >> 5;
    int g = lane >> 2, tig = lane & 3;
    int wm = (warp & 3) * 32, wn = (warp >> 2) * 64;
    float c[2][8][4] = {};
    for (int kt = 0; kt < 8; kt++) {
        __syncthreads();
#pragma unroll
        for (int t = 0; t < 4; t++) {
            int idx = tid + 256 * t;
            int m = idx >> 3, kq = idx & 7;
            *(float4*)&As[m][kq*4] = *(const float4*)(g_o + (size_t)(bm*128+m)*256 + kt*32 + kq*4);
            int k = idx >> 5, nq = idx & 31;
            *(float4*)&Bs[k][nq*4] = *(const float4*)(Wo + (size_t)(kt*32+k)*128 + nq*4);
        }
        __syncthreads();
#pragma unroll
        for (int k8 = 0; k8 < 4; k8++) {
            int k0 = k8 * 8;
            uint32_t a[2][4];
#pragma unroll
            for (int mi = 0; mi < 2; mi++) {
                a[mi][0] = cvt_tf32(As[wm+mi*16+g  ][k0+tig  ]);
                a[mi][1] = cvt_tf32(As[wm+mi*16+g+8][k0+tig  ]);
                a[mi][2] = cvt_tf32(As[wm+mi*16+g  ][k0+tig+4]);
                a[mi][3] = cvt_tf32(As[wm+mi*16+g+8][k0+tig+4]);
            }
#pragma unroll
            for (int ni = 0; ni < 8; ni++) {
                uint32_t bb[2];
                bb[0] = cvt_tf32(Bs[k0+tig  ][wn+ni*8+g]);
                bb[1] = cvt_tf32(Bs[k0+tig+4][wn+ni*8+g]);
#pragma unroll
                for (int mi = 0; mi < 2; mi++) mma_tf32(c[mi][ni], a[mi], bb);
            }
        }
    }
#pragma unroll
    for (int mi = 0; mi < 2; mi++) {
#pragma unroll
        for (int rsel = 0; rsel < 2; rsel++) {
            int m = bm * 128 + wm + mi * 16 + g + rsel * 8;
            float mk = mask[m];
#pragma unroll
            for (int ni = 0; ni < 8; ni++) {
                int col = wn + ni * 8 + tig * 2;
                float2 b2 = *(const float2*)(bo + col);
                float2 o2;
                o2.x = (c[mi][ni][rsel*2+0] + b2.x) * mk;
                o2.y = (c[mi][ni][rsel*2+1] + b2.y) * mk;
                *(float2*)(out + (size_t)m * 128 + col) = o2;
            }
        }
    }
}

// ---------------- launch ----------------
extern "C" void kernel_launch(void* const* d_in, const int* in_sizes, int n_in,
                              void* d_out, int out_size) {
    const float* pair_rep = (const float*)d_in[0];
    const float* mask     = (const float*)d_in[1];
    const float* gamma    = (const float*)d_in[2];
    const float* beta     = (const float*)d_in[3];
    const float* Wq       = (const float*)d_in[4];
    const float* Wk       = (const float*)d_in[5];
    const float* Wv       = (const float*)d_in[6];
    const float* Wb       = (const float*)d_in[7];
    const float* Wu       = (const float*)d_in[8];
    const float* bu       = (const float*)d_in[9];
    const float* Wo       = (const float*)d_in[10];
    const float* bo       = (const float*)d_in[11];
    float* out = (float*)d_out;

    cudaFuncSetAttribute(attn_kernel, cudaFuncAttributeMaxDynamicSharedMemorySize, ATTN_SMEM);

    ln_kernel<<<8192, 256>>>(pair_rep, gamma, beta);
    proj_kernel<0, true ><<<dim3(512, 4), 256>>>(Wq, Wk, bu);
    proj_kernel<2, false><<<dim3(512, 4), 256>>>(Wv, Wu, bu);
    bias_kernel<<<8192, 256>>>(Wb, mask);
    attn_kernel<<<4096, 512, ATTN_SMEM>>>();
    out_kernel<<<512, 256>>>(Wo, bo, mask, out);
}

// round 6
// speedup vs baseline: 2.6192x; 1.8568x over previous
#include <cuda_runtime.h>
#include <cuda_fp16.h>
#include <cstdint>

#define LL 256
#define HC 256
#define NROWS (LL*LL)   // 65536

// ---------------- scratch (static device globals; no allocations) ----------
__device__ __align__(16) float  g_x [NROWS*128];      // layernorm out fp32 (for bias path)
__device__ __align__(16) __half g_xs[NROWS*256];      // layernorm out split: [row][0:128 hi | 128:256 lo]
__device__ __align__(16) __half g_qs[NROWS*512];      // q split  [(s,h,r)][0:64 hi | 64:128 lo] (pre-scaled)
__device__ __align__(16) __half g_ks[NROWS*512];      // k split  same layout
__device__ __align__(16) __half g_vh[NROWS*256];      // v half   [(s,h,r)][c]
__device__ __align__(16) float  g_u [NROWS*256];      // sigmoid gate fp32 [(s,h,r)][c]
__device__ __align__(16) float  g_bias[4*NROWS];      // pair_bias + mask bias [h][q][v]
__device__ __align__(16) float  g_o [NROWS*256];      // attention out fp32 [s*256+q][h*64+c]
// pre-transposed / split weights [n][k] half
__device__ __align__(16) __half g_Wqt_h[256*128], g_Wqt_l[256*128];
__device__ __align__(16) __half g_Wkt_h[256*128], g_Wkt_l[256*128];
__device__ __align__(16) __half g_Wvt[256*128], g_Wut[256*128];
__device__ __align__(16) __half g_Wot[128*256];

// ---------------- mma / ldmatrix helpers ----------------
__device__ __forceinline__ uint32_t sm_addr(const void* p) {
    return (uint32_t)__cvta_generic_to_shared(p);
}
__device__ __forceinline__ void ldm_x4(uint32_t* r, uint32_t a) {
    asm volatile("ldmatrix.sync.aligned.m8n8.x4.shared.b16 {%0,%1,%2,%3}, [%4];"
                 : "=r"(r[0]), "=r"(r[1]), "=r"(r[2]), "=r"(r[3]) : "r"(a));
}
__device__ __forceinline__ void ldm_x4_t(uint32_t* r, uint32_t a) {
    asm volatile("ldmatrix.sync.aligned.m8n8.x4.trans.shared.b16 {%0,%1,%2,%3}, [%4];"
                 : "=r"(r[0]), "=r"(r[1]), "=r"(r[2]), "=r"(r[3]) : "r"(a));
}
__device__ __forceinline__ void mma_f16(float* c, const uint32_t* a, const uint32_t* b) {
    asm volatile("mma.sync.aligned.m16n8k16.row.col.f32.f16.f16.f32 "
                 "{%0,%1,%2,%3},{%4,%5,%6,%7},{%8,%9},{%0,%1,%2,%3};"
                 : "+f"(c[0]), "+f"(c[1]), "+f"(c[2]), "+f"(c[3])
                 : "r"(a[0]), "r"(a[1]), "r"(a[2]), "r"(a[3]), "r"(b[0]), "r"(b[1]));
}
// one address formula for A / B(non-trans from [n][k]) / B(trans from [k][n]) tiles
template<int STRIDE>
__device__ __forceinline__ uint32_t qaddr(uint32_t base, int r0, int c0, int lane) {
    int t = lane >> 3, tr = lane & 7;
    return base + (uint32_t)(((r0 + tr + (t & 1) * 8) * STRIDE + c0 + (t >> 1) * 8) * 2);
}
__device__ __forceinline__ uint32_t pack2(float x, float y) {
    __half2 h = __floats2half2_rn(x, y);
    return *(uint32_t*)&h;
}

// ---------------- kernel 0: weight transpose + split ----------------
__global__ void prep_kernel(const float* __restrict__ Wq, const float* __restrict__ Wk,
                            const float* __restrict__ Wv, const float* __restrict__ Wu,
                            const float* __restrict__ Wo) {
    for (int idx = blockIdx.x * 256 + threadIdx.x; idx < 32768; idx += gridDim.x * 256) {
        int k = idx >> 8, n = idx & 255;
        float xq = Wq[idx]; __half hq = __float2half_rn(xq);
        g_Wqt_h[n*128+k] = hq; g_Wqt_l[n*128+k] = __float2half_rn(xq - __half2float(hq));
        float xk = Wk[idx]; __half hk = __float2half_rn(xk);
        g_Wkt_h[n*128+k] = hk; g_Wkt_l[n*128+k] = __float2half_rn(xk - __half2float(hk));
        g_Wvt[n*128+k] = __float2half_rn(Wv[idx]);
        g_Wut[n*128+k] = __float2half_rn(Wu[idx]);
        int k2 = idx >> 7, n2 = idx & 127;
        g_Wot[n2*256+k2] = __float2half_rn(Wo[idx]);
    }
}

// ---------------- kernel 1: layernorm (fp32 + split-half out) ----------------
__global__ __launch_bounds__(256) void ln_kernel(const float* __restrict__ in,
                                                 const float* __restrict__ gamma,
                                                 const float* __restrict__ beta) {
    int row  = blockIdx.x * 8 + (threadIdx.x >> 5);
    int lane = threadIdx.x & 31;
    float4 v = reinterpret_cast<const float4*>(in)[(size_t)row * 32 + lane];
    float s  = v.x + v.y + v.z + v.w;
    float ss = v.x*v.x + v.y*v.y + v.z*v.z + v.w*v.w;
#pragma unroll
    for (int o = 16; o; o >>= 1) {
        s  += __shfl_xor_sync(0xffffffffu, s,  o);
        ss += __shfl_xor_sync(0xffffffffu, ss, o);
    }
    float mu  = s * (1.f / 128.f);
    float var = fmaxf(ss * (1.f / 128.f) - mu * mu, 0.f);
    float inv = rsqrtf(var + 1e-5f);
    float4 g = reinterpret_cast<const float4*>(gamma)[lane];
    float4 b = reinterpret_cast<const float4*>(beta)[lane];
    float o4[4];
    o4[0] = (v.x - mu) * inv * g.x + b.x;
    o4[1] = (v.y - mu) * inv * g.y + b.y;
    o4[2] = (v.z - mu) * inv * g.z + b.z;
    o4[3] = (v.w - mu) * inv * g.w + b.w;
    reinterpret_cast<float4*>(g_x)[(size_t)row * 32 + lane] = make_float4(o4[0], o4[1], o4[2], o4[3]);
    __half h[4]; float l[4];
#pragma unroll
    for (int i = 0; i < 4; i++) { h[i] = __float2half_rn(o4[i]); l[i] = o4[i] - __half2float(h[i]); }
    uint2 hi2 = make_uint2(pack2(__half2float(h[0]), __half2float(h[1])),
                           pack2(__half2float(h[2]), __half2float(h[3])));
    uint2 lo2 = make_uint2(pack2(l[0], l[1]), pack2(l[2], l[3]));
    uint2* dst = (uint2*)(g_xs + (size_t)row * 256);
    dst[lane] = hi2;
    dst[32 + lane] = lo2;
}

// ---------------- kernel 2: pair_bias + mask bias (reduction-free) ----------
__global__ __launch_bounds__(256) void bias_kernel(const float* __restrict__ Wb,
                                                   const float* __restrict__ mask) {
    __shared__ float Xs[64][132];
    __shared__ float Wbs[4][132];
    int p0 = blockIdx.x * 64;
    int tid = threadIdx.x;
#pragma unroll
    for (int t = 0; t < 2; t++) {
        int idx = tid + 256 * t;
        Wbs[idx & 3][idx >> 2] = Wb[idx];
    }
#pragma unroll
    for (int i = 0; i < 8; i++) {
        int idx = tid + 256 * i;
        int row = idx >> 5, c = idx & 31;
        *(float4*)&Xs[row][c*4] = reinterpret_cast<const float4*>(g_x)[(size_t)(p0+row)*32 + c];
    }
    __syncthreads();
    int p = tid >> 2, hh = tid & 3;
    float acc = 0.f;
#pragma unroll
    for (int i = 0; i < 32; i++) {
        float4 xv = *(float4*)&Xs[p][i*4];
        float4 wv = *(float4*)&Wbs[hh][i*4];
        acc += xv.x*wv.x + xv.y*wv.y + xv.z*wv.z + xv.w*wv.w;
    }
    int pair = p0 + p;
    g_bias[(size_t)hh * 65536 + pair] = acc + 1e9f * (mask[pair] - 1.f);
}

// ---------------- kernel 3: split projection GEMM (Q,K) ----------------
// M=65536, N=512 (q|k of 256), K=128. CTA 128x128, 8 warps 32x64, 3-mma fp16 split.
#define PROJS_SMEM (128*136*2 + 2*128*72*2)   // As + Bh + Bl = 71680
__global__ __launch_bounds__(256) void proj_split_kernel() {
    extern __shared__ char smem[];
    __half* As = (__half*)smem;                      // [128][136] hi|lo per k-chunk
    __half* Bh = (__half*)(smem + 128*136*2);        // [128][72]
    __half* Bl = (__half*)(smem + 128*136*2 + 128*72*2);
    int bm = blockIdx.x, bn = blockIdx.y;
    int mat = bn >> 1;                               // 0:q 1:k
    int ncol0 = (bn & 1) * 128;
    const __half* Wh = mat ? g_Wkt_h : g_Wqt_h;
    const __half* Wl = mat ? g_Wkt_l : g_Wqt_l;
    int tid = threadIdx.x, lane = tid & 31, w = tid >> 5;
    int g = lane >> 2, tig = lane & 3;
    int wm = (w & 3) * 32, wn = (w >> 2) * 64;
    uint32_t asb = sm_addr(As), bhb = sm_addr(Bh), blb = sm_addr(Bl);
    float c[2][8][4] = {};
    for (int kt = 0; kt < 2; kt++) {
        __syncthreads();
#pragma unroll
        for (int t = 0; t < 8; t++) {
            int idx = tid + 256 * t;
            int row = idx >> 4, cc = idx & 15;
            int src = (cc < 8) ? (kt*8 + cc) : (16 + kt*8 + (cc-8));
            *(uint4*)&As[row*136 + cc*8] =
                reinterpret_cast<const uint4*>(g_xs)[(size_t)(bm*128+row)*32 + src];
        }
#pragma unroll
        for (int t = 0; t < 4; t++) {
            int idx = tid + 256 * t;
            int row = idx >> 3, cc = idx & 7;
            *(uint4*)&Bh[row*72 + cc*8] =
                reinterpret_cast<const uint4*>(Wh)[(size_t)(ncol0+row)*16 + kt*8 + cc];
            *(uint4*)&Bl[row*72 + cc*8] =
                reinterpret_cast<const uint4*>(Wl)[(size_t)(ncol0+row)*16 + kt*8 + cc];
        }
        __syncthreads();
#pragma unroll
        for (int ki = 0; ki < 4; ki++) {
            uint32_t ah[2][4], al[2][4];
#pragma unroll
            for (int mt = 0; mt < 2; mt++) {
                ldm_x4(ah[mt], qaddr<136>(asb, wm + mt*16, ki*16, lane));
                ldm_x4(al[mt], qaddr<136>(asb, wm + mt*16, 64 + ki*16, lane));
            }
#pragma unroll
            for (int nf = 0; nf < 4; nf++) {
                uint32_t bh[4], bl[4];
                ldm_x4(bh, qaddr<72>(bhb, wn + nf*16, ki*16, lane));
                ldm_x4(bl, qaddr<72>(blb, wn + nf*16, ki*16, lane));
                uint32_t b0h[2] = {bh[0], bh[2]}, b1h[2] = {bh[1], bh[3]};
                uint32_t b0l[2] = {bl[0], bl[2]}, b1l[2] = {bl[1], bl[3]};
#pragma unroll
                for (int mt = 0; mt < 2; mt++) {
                    mma_f16(c[mt][nf*2],   ah[mt], b0h);
                    mma_f16(c[mt][nf*2],   al[mt], b0h);
                    mma_f16(c[mt][nf*2],   ah[mt], b0l);
                    mma_f16(c[mt][nf*2+1], ah[mt], b1h);
                    mma_f16(c[mt][nf*2+1], al[mt], b1h);
                    mma_f16(c[mt][nf*2+1], ah[mt], b1l);
                }
            }
        }
    }
    // epilogue: split fp32 -> (hi,lo) half pairs, scatter to [s,h,r,c] layout
    __half* dst = mat ? g_ks : g_qs;
    float scale = mat ? 1.f : 0.125f;
#pragma unroll
    for (int mt = 0; mt < 2; mt++) {
#pragma unroll
        for (int rs = 0; rs < 2; rs++) {
            int m = bm*128 + wm + mt*16 + g + rs*8;
            int si = m >> 8, rr = m & 255;
#pragma unroll
            for (int ni = 0; ni < 8; ni++) {
                int col = ncol0 + wn + ni*8 + tig*2;
                int head = col >> 6, cc = col & 63;
                size_t drow = ((size_t)(si*4 + head))*256 + rr;
                float v0 = c[mt][ni][rs*2+0] * scale;
                float v1 = c[mt][ni][rs*2+1] * scale;
                __half h0 = __float2half_rn(v0), h1 = __float2half_rn(v1);
                float l0 = v0 - __half2float(h0), l1 = v1 - __half2float(h1);
                *(uint32_t*)(dst + drow*128 + cc)      = pack2(__half2float(h0), __half2float(h1));
                *(uint32_t*)(dst + drow*128 + 64 + cc) = pack2(l0, l1);
            }
        }
    }
}

// ---------------- kernel 4: single-fp16 projection GEMM (V,U) ----------------
__global__ __launch_bounds__(256) void proj_single_kernel(const float* __restrict__ bu) {
    __shared__ __half As[128*72];
    __shared__ __half Bs[128*72];
    int bm = blockIdx.x, bn = blockIdx.y;
    int mat = bn >> 1;                  // 0:v 1:u
    int ncol0 = (bn & 1) * 128;
    const __half* W = mat ? g_Wut : g_Wvt;
    int tid = threadIdx.x, lane = tid & 31, w = tid >> 5;
    int g = lane >> 2, tig = lane & 3;
    int wm = (w & 3) * 32, wn = (w >> 2) * 64;
    uint32_t asb = sm_addr(As), bsb = sm_addr(Bs);
    float c[2][8][4] = {};
    for (int kt = 0; kt < 2; kt++) {
        __syncthreads();
#pragma unroll
        for (int t = 0; t < 4; t++) {
            int idx = tid + 256 * t;
            int row = idx >> 3, cc = idx & 7;
            *(uint4*)&As[row*72 + cc*8] =
                reinterpret_cast<const uint4*>(g_xs)[(size_t)(bm*128+row)*32 + kt*8 + cc];
            *(uint4*)&Bs[row*72 + cc*8] =
                reinterpret_cast<const uint4*>(W)[(size_t)(ncol0+row)*16 + kt*8 + cc];
        }
        __syncthreads();
#pragma unroll
        for (int ki = 0; ki < 4; ki++) {
            uint32_t a[2][4];
#pragma unroll
            for (int mt = 0; mt < 2; mt++)
                ldm_x4(a[mt], qaddr<72>(asb, wm + mt*16, ki*16, lane));
#pragma unroll
            for (int nf = 0; nf < 4; nf++) {
                uint32_t b[4];
                ldm_x4(b, qaddr<72>(bsb, wn + nf*16, ki*16, lane));
                uint32_t b0[2] = {b[0], b[2]}, b1[2] = {b[1], b[3]};
#pragma unroll
                for (int mt = 0; mt < 2; mt++) {
                    mma_f16(c[mt][nf*2],   a[mt], b0);
                    mma_f16(c[mt][nf*2+1], a[mt], b1);
                }
            }
        }
    }
#pragma unroll
    for (int mt = 0; mt < 2; mt++) {
#pragma unroll
        for (int rs = 0; rs < 2; rs++) {
            int m = bm*128 + wm + mt*16 + g + rs*8;
            int si = m >> 8, rr = m & 255;
#pragma unroll
            for (int ni = 0; ni < 8; ni++) {
                int col = ncol0 + wn + ni*8 + tig*2;
                int head = col >> 6, cc = col & 63;
                size_t drow = ((size_t)(si*4 + head))*256 + rr;
                float v0 = c[mt][ni][rs*2+0], v1 = c[mt][ni][rs*2+1];
                if (mat == 0) {
                    *(uint32_t*)(g_vh + drow*64 + cc) = pack2(v0, v1);
                } else {
                    float2 b2 = *(const float2*)(bu + col);
                    float u0 = 1.f / (1.f + __expf(-(v0 + b2.x)));
                    float u1 = 1.f / (1.f + __expf(-(v1 + b2.y)));
                    *(float2*)(g_u + drow*64 + cc) = make_float2(u0, u1);
                }
            }
        }
    }
}

// ---------------- kernel 5: attention per (s, h, q-tile of 64) ----------------
// smem: Ks[64][136]h | Qs[256][136]h (Vs[256][72]h overlay) | Ph[64][264]h | Ored[64][68]f | red
#define OFF_QS 17408
#define OFF_PH 87040
#define OFF_OR 120832
#define OFF_WM 138240
#define OFF_WS 139264
#define OFF_RI 140288
#define ATTN_SMEM 140544
__global__ __launch_bounds__(512) void attn_kernel() {
    extern __shared__ char smem[];
    __half* Ks = (__half*)smem;
    __half* Qs = (__half*)(smem + OFF_QS);
    __half* Vs = (__half*)(smem + OFF_QS);
    __half* Ph = (__half*)(smem + OFF_PH);
    float* Ored = (float*)(smem + OFF_OR);
    float* wmax = (float*)(smem + OFF_WM);
    float* wsum = (float*)(smem + OFF_WS);
    float* rinv = (float*)(smem + OFF_RI);

    int b = blockIdx.x;
    int s = b >> 4, h = (b >> 2) & 3, qt = b & 3;
    int tid = threadIdx.x, lane = tid & 31, w = tid >> 5;
    int g = lane >> 2, tig = lane & 3;
    size_t base = ((size_t)(s*4 + h)) * 256;        // row base into (s,h,r) arrays

    // loads: K tile (64 rows x 16 uint4) and full Q (256 rows x 16 uint4), hi|lo split rows
#pragma unroll
    for (int t = 0; t < 2; t++) {
        int idx = tid + 512 * t;
        int r = idx >> 4, cc = idx & 15;
        *(uint4*)&Ks[r*136 + cc*8] =
            reinterpret_cast<const uint4*>(g_ks)[(base + qt*64 + r)*16 + cc];
    }
#pragma unroll
    for (int t = 0; t < 8; t++) {
        int idx = tid + 512 * t;
        int r = idx >> 4, cc = idx & 15;
        *(uint4*)&Qs[r*136 + cc*8] =
            reinterpret_cast<const uint4*>(g_qs)[(base + r)*16 + cc];
    }
    __syncthreads();

    // ---- S = K @ Q^T (split fp16, 3-mma): warp (wq,wv) tile 16q x 64v ----
    int wq = w & 3, wv = w >> 2;
    int q0 = wq * 16, v0 = wv * 64;
    uint32_t ksb = sm_addr(Ks), qsb = sm_addr(Qs);
    float c[8][4] = {};
#pragma unroll
    for (int kt = 0; kt < 4; kt++) {
        uint32_t ah[4], al[4];
        ldm_x4(ah, qaddr<136>(ksb, q0, kt*16, lane));
        ldm_x4(al, qaddr<136>(ksb, q0, 64 + kt*16, lane));
#pragma unroll
        for (int nf = 0; nf < 4; nf++) {
            uint32_t bh[4], bl[4];
            ldm_x4(bh, qaddr<136>(qsb, v0 + nf*16, kt*16, lane));
            ldm_x4(bl, qaddr<136>(qsb, v0 + nf*16, 64 + kt*16, lane));
            uint32_t b0h[2] = {bh[0], bh[2]}, b1h[2] = {bh[1], bh[3]};
            uint32_t b0l[2] = {bl[0], bl[2]}, b1l[2] = {bl[1], bl[3]};
            mma_f16(c[nf*2],   ah, b0h);
            mma_f16(c[nf*2],   al, b0h);
            mma_f16(c[nf*2],   ah, b0l);
            mma_f16(c[nf*2+1], ah, b1h);
            mma_f16(c[nf*2+1], al, b1h);
            mma_f16(c[nf*2+1], ah, b1l);
        }
    }

    // ---- bias add + register softmax ----
    int qg0 = qt * 64;
    const float* bp = g_bias + ((size_t)h*256 + qg0 + q0) * 256;
    float m0 = -3e38f, m1 = -3e38f;
#pragma unroll
    for (int ni = 0; ni < 8; ni++) {
        int v = v0 + ni*8 + tig*2;
        float2 b0 = *(const float2*)(bp + (size_t)g*256 + v);
        float2 b1 = *(const float2*)(bp + (size_t)(g+8)*256 + v);
        c[ni][0] += b0.x; c[ni][1] += b0.y; c[ni][2] += b1.x; c[ni][3] += b1.y;
        m0 = fmaxf(m0, fmaxf(c[ni][0], c[ni][1]));
        m1 = fmaxf(m1, fmaxf(c[ni][2], c[ni][3]));
    }
    m0 = fmaxf(m0, __shfl_xor_sync(~0u, m0, 1)); m0 = fmaxf(m0, __shfl_xor_sync(~0u, m0, 2));
    m1 = fmaxf(m1, __shfl_xor_sync(~0u, m1, 1)); m1 = fmaxf(m1, __shfl_xor_sync(~0u, m1, 2));
    if (tig == 0) { wmax[wv*64 + q0 + g] = m0; wmax[wv*64 + q0 + g + 8] = m1; }
    __syncthreads();

    // load V (overlays Qs; all warps finished S mma): 256 rows x 8 uint4
#pragma unroll
    for (int t = 0; t < 4; t++) {
        int idx = tid + 512 * t;
        int r = idx >> 3, cc = idx & 7;
        *(uint4*)&Vs[r*72 + cc*8] =
            reinterpret_cast<const uint4*>(g_vh)[(base + r)*8 + cc];
    }

    float M0 = fmaxf(fmaxf(wmax[q0+g],     wmax[64+q0+g]),
                     fmaxf(wmax[128+q0+g], wmax[192+q0+g]));
    float M1 = fmaxf(fmaxf(wmax[q0+g+8],     wmax[64+q0+g+8]),
                     fmaxf(wmax[128+q0+g+8], wmax[192+q0+g+8]));
    float s0 = 0.f, s1 = 0.f;
#pragma unroll
    for (int ni = 0; ni < 8; ni++) {
        c[ni][0] = __expf(c[ni][0] - M0); c[ni][1] = __expf(c[ni][1] - M0);
        c[ni][2] = __expf(c[ni][2] - M1); c[ni][3] = __expf(c[ni][3] - M1);
        s0 += c[ni][0] + c[ni][1];
        s1 += c[ni][2] + c[ni][3];
        int v = v0 + ni*8 + tig*2;
        *(uint32_t*)&Ph[(q0+g)*264 + v]   = pack2(c[ni][0], c[ni][1]);
        *(uint32_t*)&Ph[(q0+g+8)*264 + v] = pack2(c[ni][2], c[ni][3]);
    }
    s0 += __shfl_xor_sync(~0u, s0, 1); s0 += __shfl_xor_sync(~0u, s0, 2);
    s1 += __shfl_xor_sync(~0u, s1, 1); s1 += __shfl_xor_sync(~0u, s1, 2);
    if (tig == 0) { wsum[wv*64 + q0 + g] = s0; wsum[wv*64 + q0 + g + 8] = s1; }
    __syncthreads();
    if (tid < 64)
        rinv[tid] = 1.f / (wsum[tid] + wsum[64+tid] + wsum[128+tid] + wsum[192+tid]);

    // ---- O = P @ V (single fp16): warp (wq2,wc,wv2) tile 16q x 32c, v-half 128 ----
    int wq2 = w & 3, wc = (w >> 2) & 1, wv2 = w >> 3;
    int pq0 = wq2 * 16, c0 = wc * 32, kb = wv2 * 128;
    uint32_t phb = sm_addr(Ph), vsb = sm_addr(Vs);
    float oc[4][4] = {};
#pragma unroll
    for (int kt = 0; kt < 8; kt++) {
        uint32_t a[4], bA[4], bB[4];
        ldm_x4(a, qaddr<264>(phb, pq0, kb + kt*16, lane));
        ldm_x4_t(bA, qaddr<72>(vsb, kb + kt*16, c0, lane));
        ldm_x4_t(bB, qaddr<72>(vsb, kb + kt*16, c0 + 16, lane));
        uint32_t f0[2] = {bA[0], bA[1]}, f1[2] = {bA[2], bA[3]};
        uint32_t f2[2] = {bB[0], bB[1]}, f3[2] = {bB[2], bB[3]};
        mma_f16(oc[0], a, f0); mma_f16(oc[1], a, f1);
        mma_f16(oc[2], a, f2); mma_f16(oc[3], a, f3);
    }
    if (wv2 == 1) {
#pragma unroll
        for (int j = 0; j < 4; j++) {
            int ccol = c0 + j*8 + tig*2;
            *(float2*)&Ored[(pq0+g)*68 + ccol]   = make_float2(oc[j][0], oc[j][1]);
            *(float2*)&Ored[(pq0+g+8)*68 + ccol] = make_float2(oc[j][2], oc[j][3]);
        }
    }
    __syncthreads();
    if (wv2 == 0) {
        float rv0 = rinv[pq0 + g], rv1 = rinv[pq0 + g + 8];
        int qgA = qt*64 + pq0 + g, qgB = qgA + 8;
#pragma unroll
        for (int j = 0; j < 4; j++) {
            int ccol = c0 + j*8 + tig*2;
            float2 p0 = *(float2*)&Ored[(pq0+g)*68 + ccol];
            float2 p1 = *(float2*)&Ored[(pq0+g+8)*68 + ccol];
            float2 u0 = *(const float2*)(g_u + (base + qgA)*64 + ccol);
            float2 u1 = *(const float2*)(g_u + (base + qgB)*64 + ccol);
            float2 oA = make_float2((oc[j][0] + p0.x) * rv0 * u0.x,
                                    (oc[j][1] + p0.y) * rv0 * u0.y);
            float2 oB = make_float2((oc[j][2] + p1.x) * rv1 * u1.x,
                                    (oc[j][3] + p1.y) * rv1 * u1.y);
            *(float2*)(g_o + ((size_t)(s*256 + qgA))*256 + h*64 + ccol) = oA;
            *(float2*)(g_o + ((size_t)(s*256 + qgB))*256 + h*64 + ccol) = oB;
        }
    }
}

// ---------------- kernel 6: output GEMM (single fp16) ----------------
#define OUT_SMEM (128*136*2*2)
__global__ __launch_bounds__(256) void out_kernel(const float* __restrict__ bo,
                                                  const float* __restrict__ mask,
                                                  float* __restrict__ out) {
    extern __shared__ char smem[];
    __half* As = (__half*)smem;                  // [128][136]
    __half* Bs = (__half*)(smem + 128*136*2);    // [128][136]
    int bm = blockIdx.x;
    int tid = threadIdx.x, lane = tid & 31, w = tid >> 5;
    int g = lane >> 2, tig = lane & 3;
    int wm = (w & 3) * 32, wn = (w >> 2) * 64;
    uint32_t asb = sm_addr(As), bsb = sm_addr(Bs);
    float c[2][8][4] = {};
    for (int kt = 0; kt < 2; kt++) {
        __syncthreads();
#pragma unroll
        for (int t = 0; t < 16; t++) {
            int idx = tid + 256 * t;
            int row = idx >> 5, cq = idx & 31;
            float4 a = reinterpret_cast<const float4*>(g_o)[(size_t)(bm*128+row)*64 + kt*32 + cq];
            *(uint2*)&As[row*136 + cq*4] =
                make_uint2(pack2(a.x, a.y), pack2(a.z, a.w));
        }
#pragma unroll
        for (int t = 0; t < 8; t++) {
            int idx = tid + 256 * t;
            int row = idx >> 4, cc = idx & 15;
            *(uint4*)&Bs[row*136 + cc*8] =
                reinterpret_cast<const uint4*>(g_Wot)[(size_t)row*32 + kt*16 + cc];
        }
        __syncthreads();
#pragma unroll
        for (int ki = 0; ki < 8; ki++) {
            uint32_t a[2][4];
#pragma unroll
            for (int mt = 0; mt < 2; mt++)
                ldm_x4(a[mt], qaddr<136>(asb, wm + mt*16, ki*16, lane));
#pragma unroll
            for (int nf = 0; nf < 4; nf++) {
                uint32_t b[4];
                ldm_x4(b, qaddr<136>(bsb, wn + nf*16, ki*16, lane));
                uint32_t b0[2] = {b[0], b[2]}, b1[2] = {b[1], b[3]};
#pragma unroll
                for (int mt = 0; mt < 2; mt++) {
                    mma_f16(c[mt][nf*2],   a[mt], b0);
                    mma_f16(c[mt][nf*2+1], a[mt], b1);
                }
            }
        }
    }
#pragma unroll
    for (int mt = 0; mt < 2; mt++) {
#pragma unroll
        for (int rs = 0; rs < 2; rs++) {
            int m = bm*128 + wm + mt*16 + g + rs*8;
            float mk = mask[m];
#pragma unroll
            for (int ni = 0; ni < 8; ni++) {
                int col = wn + ni*8 + tig*2;
                float2 b2 = *(const float2*)(bo + col);
                float2 o2 = make_float2((c[mt][ni][rs*2+0] + b2.x) * mk,
                                        (c[mt][ni][rs*2+1] + b2.y) * mk);
                *(float2*)(out + (size_t)m * 128 + col) = o2;
            }
        }
    }
}

// ---------------- launch ----------------
extern "C" void kernel_launch(void* const* d_in, const int* in_sizes, int n_in,
                              void* d_out, int out_size) {
    const float* pair_rep = (const float*)d_in[0];
    const float* mask     = (const float*)d_in[1];
    const float* gamma    = (const float*)d_in[2];
    const float* beta     = (const float*)d_in[3];
    const float* Wq       = (const float*)d_in[4];
    const float* Wk       = (const float*)d_in[5];
    const float* Wv       = (const float*)d_in[6];
    const float* Wb       = (const float*)d_in[7];
    const float* Wu       = (const float*)d_in[8];
    const float* bu       = (const float*)d_in[9];
    const float* Wo       = (const float*)d_in[10];
    const float* bo       = (const float*)d_in[11];
    float* out = (float*)d_out;

    cudaFuncSetAttribute(attn_kernel, cudaFuncAttributeMaxDynamicSharedMemorySize, ATTN_SMEM);
    cudaFuncSetAttribute(proj_split_kernel, cudaFuncAttributeMaxDynamicSharedMemorySize, PROJS_SMEM);
    cudaFuncSetAttribute(out_kernel, cudaFuncAttributeMaxDynamicSharedMemorySize, OUT_SMEM);

    prep_kernel<<<64, 256>>>(Wq, Wk, Wv, Wu, Wo);
    ln_kernel<<<8192, 256>>>(pair_rep, gamma, beta);
    bias_kernel<<<1024, 256>>>(Wb, mask);
    proj_split_kernel<<<dim3(512, 4), 256, PROJS_SMEM>>>();
    proj_single_kernel<<<dim3(512, 4), 256>>>(bu);
    attn_kernel<<<4096, 512, ATTN_SMEM>>>();
    out_kernel<<<512, 256, OUT_SMEM>>>(bo, mask, out);
}

// round 10
// speedup vs baseline: 2.6859x; 1.0255x over previous
#include <cuda_runtime.h>
#include <cuda_fp16.h>
#include <cstdint>

#define LL 256
#define HC 256
#define NROWS (LL*LL)   // 65536

// ---------------- scratch (static device globals; no allocations) ----------
__device__ __align__(16) __half g_xs[NROWS*256];      // layernorm out split: [row][0:128 hi | 128:256 lo]
__device__ __align__(16) __half g_qs[NROWS*512];      // q split  [(s,h,r)][0:64 hi | 64:128 lo] (pre-scaled)
__device__ __align__(16) __half g_ks[NROWS*512];      // k split  same layout
__device__ __align__(16) __half g_vh[NROWS*256];      // v half   [(s,h,r)][c]
__device__ __align__(16) float  g_u [NROWS*256];      // sigmoid gate fp32 [(s,h,r)][c]
__device__ __align__(16) float  g_bias[4*NROWS];      // pair_bias + mask bias [h][q][v]
__device__ __align__(16) __half g_oh[NROWS*256];      // attention out half [s*256+q][h*64+c]
// pre-transposed / split weights [n][k] half
__device__ __align__(16) __half g_Wqt_h[256*128], g_Wqt_l[256*128];
__device__ __align__(16) __half g_Wkt_h[256*128], g_Wkt_l[256*128];
__device__ __align__(16) __half g_Wvt[256*128], g_Wut[256*128];
__device__ __align__(16) __half g_Wot[128*256];

// ---------------- mma / ldmatrix helpers ----------------
__device__ __forceinline__ uint32_t sm_addr(const void* p) {
    return (uint32_t)__cvta_generic_to_shared(p);
}
__device__ __forceinline__ void ldm_x4(uint32_t* r, uint32_t a) {
    asm volatile("ldmatrix.sync.aligned.m8n8.x4.shared.b16 {%0,%1,%2,%3}, [%4];"
                 : "=r"(r[0]), "=r"(r[1]), "=r"(r[2]), "=r"(r[3]) : "r"(a));
}
__device__ __forceinline__ void ldm_x4_t(uint32_t* r, uint32_t a) {
    asm volatile("ldmatrix.sync.aligned.m8n8.x4.trans.shared.b16 {%0,%1,%2,%3}, [%4];"
                 : "=r"(r[0]), "=r"(r[1]), "=r"(r[2]), "=r"(r[3]) : "r"(a));
}
__device__ __forceinline__ void mma_f16(float* c, const uint32_t* a, const uint32_t* b) {
    asm volatile("mma.sync.aligned.m16n8k16.row.col.f32.f16.f16.f32 "
                 "{%0,%1,%2,%3},{%4,%5,%6,%7},{%8,%9},{%0,%1,%2,%3};"
                 : "+f"(c[0]), "+f"(c[1]), "+f"(c[2]), "+f"(c[3])
                 : "r"(a[0]), "r"(a[1]), "r"(a[2]), "r"(a[3]), "r"(b[0]), "r"(b[1]));
}
template<int STRIDE>
__device__ __forceinline__ uint32_t qaddr(uint32_t base, int r0, int c0, int lane) {
    int t = lane >> 3, tr = lane & 7;
    return base + (uint32_t)(((r0 + tr + (t & 1) * 8) * STRIDE + c0 + (t >> 1) * 8) * 2);
}
__device__ __forceinline__ uint32_t pack2(float x, float y) {
    __half2 h = __floats2half2_rn(x, y);
    return *(uint32_t*)&h;
}

// ---------------- kernel 0: weight transpose + split ----------------
__global__ void prep_kernel(const float* __restrict__ Wq, const float* __restrict__ Wk,
                            const float* __restrict__ Wv, const float* __restrict__ Wu,
                            const float* __restrict__ Wo) {
    for (int idx = blockIdx.x * 256 + threadIdx.x; idx < 32768; idx += gridDim.x * 256) {
        int k = idx >> 8, n = idx & 255;
        float xq = Wq[idx]; __half hq = __float2half_rn(xq);
        g_Wqt_h[n*128+k] = hq; g_Wqt_l[n*128+k] = __float2half_rn(xq - __half2float(hq));
        float xk = Wk[idx]; __half hk = __float2half_rn(xk);
        g_Wkt_h[n*128+k] = hk; g_Wkt_l[n*128+k] = __float2half_rn(xk - __half2float(hk));
        g_Wvt[n*128+k] = __float2half_rn(Wv[idx]);
        g_Wut[n*128+k] = __float2half_rn(Wu[idx]);
        int k2 = idx >> 7, n2 = idx & 127;
        g_Wot[n2*256+k2] = __float2half_rn(Wo[idx]);
    }
}

// ---------------- kernel 1: layernorm (split-half out only) ----------------
__global__ __launch_bounds__(256) void ln_kernel(const float* __restrict__ in,
                                                 const float* __restrict__ gamma,
                                                 const float* __restrict__ beta) {
    int row  = blockIdx.x * 8 + (threadIdx.x >> 5);
    int lane = threadIdx.x & 31;
    float4 v = reinterpret_cast<const float4*>(in)[(size_t)row * 32 + lane];
    float s  = v.x + v.y + v.z + v.w;
    float ss = v.x*v.x + v.y*v.y + v.z*v.z + v.w*v.w;
#pragma unroll
    for (int o = 16; o; o >>= 1) {
        s  += __shfl_xor_sync(0xffffffffu, s,  o);
        ss += __shfl_xor_sync(0xffffffffu, ss, o);
    }
    float mu  = s * (1.f / 128.f);
    float var = fmaxf(ss * (1.f / 128.f) - mu * mu, 0.f);
    float inv = rsqrtf(var + 1e-5f);
    float4 g = reinterpret_cast<const float4*>(gamma)[lane];
    float4 b = reinterpret_cast<const float4*>(beta)[lane];
    float o4[4];
    o4[0] = (v.x - mu) * inv * g.x + b.x;
    o4[1] = (v.y - mu) * inv * g.y + b.y;
    o4[2] = (v.z - mu) * inv * g.z + b.z;
    o4[3] = (v.w - mu) * inv * g.w + b.w;
    __half h[4]; float l[4];
#pragma unroll
    for (int i = 0; i < 4; i++) { h[i] = __float2half_rn(o4[i]); l[i] = o4[i] - __half2float(h[i]); }
    uint2 hi2 = make_uint2(pack2(__half2float(h[0]), __half2float(h[1])),
                           pack2(__half2float(h[2]), __half2float(h[3])));
    uint2 lo2 = make_uint2(pack2(l[0], l[1]), pack2(l[2], l[3]));
    uint2* dst = (uint2*)(g_xs + (size_t)row * 256);
    dst[lane] = hi2;
    dst[32 + lane] = lo2;
}

// ---------------- kernel 2: pair_bias + mask bias ----------------
__global__ __launch_bounds__(256) void bias_kernel(const float* __restrict__ Wb,
                                                   const float* __restrict__ mask) {
    __shared__ float Xs[64][132];
    __shared__ float Wbs[4][132];
    int p0 = blockIdx.x * 64;
    int tid = threadIdx.x;
#pragma unroll
    for (int t = 0; t < 2; t++) {
        int idx = tid + 256 * t;
        Wbs[idx & 3][idx >> 2] = Wb[idx];
    }
#pragma unroll
    for (int i = 0; i < 4; i++) {
        int idx = tid + 256 * i;
        int row = idx >> 4, j = idx & 15;
        const uint4* rb = reinterpret_cast<const uint4*>(g_xs + (size_t)(p0+row)*256);
        uint4 hv = rb[j], lv = rb[16 + j];
        const __half2* hp = (const __half2*)&hv;
        const __half2* lp = (const __half2*)&lv;
        float out8[8];
#pragma unroll
        for (int e = 0; e < 4; e++) {
            float2 hf = __half22float2(hp[e]);
            float2 lf = __half22float2(lp[e]);
            out8[e*2+0] = hf.x + lf.x;
            out8[e*2+1] = hf.y + lf.y;
        }
        *(float4*)&Xs[row][j*8]     = make_float4(out8[0], out8[1], out8[2], out8[3]);
        *(float4*)&Xs[row][j*8 + 4] = make_float4(out8[4], out8[5], out8[6], out8[7]);
    }
    __syncthreads();
    int p = tid >> 2, hh = tid & 3;
    float acc = 0.f;
#pragma unroll
    for (int i = 0; i < 32; i++) {
        float4 xv = *(float4*)&Xs[p][i*4];
        float4 wv = *(float4*)&Wbs[hh][i*4];
        acc += xv.x*wv.x + xv.y*wv.y + xv.z*wv.z + xv.w*wv.w;
    }
    int pair = p0 + p;
    g_bias[(size_t)hh * 65536 + pair] = acc + 1e9f * (mask[pair] - 1.f);
}

// ---------------- kernel 3: split projection GEMM (Q,K) ----------------
// CTA tile 128m x 64n, FULL K=128 resident (hi|lo). One sync, 8 k-steps.
#define PROJS_SMEM (128*264*2 + 2*64*136*2)   // 67584 + 34816 = 102400
__global__ __launch_bounds__(256) void proj_split_kernel() {
    extern __shared__ char smem[];
    __half* As = (__half*)smem;                       // [128][264]: 0..127 hi k, 128..255 lo k
    __half* Bh = (__half*)(smem + 128*264*2);         // [64][136]
    __half* Bl = (__half*)(smem + 128*264*2 + 64*136*2);
    int bm = blockIdx.x, bn = blockIdx.y;             // bn 0..7
    int mat = bn >> 2;                                // 0:q 1:k
    int ncol0 = (bn & 3) * 64;
    const __half* Wh = mat ? g_Wkt_h : g_Wqt_h;
    const __half* Wl = mat ? g_Wkt_l : g_Wqt_l;
    int tid = threadIdx.x, lane = tid & 31, w = tid >> 5;
    int g = lane >> 2, tig = lane & 3;
    int wm = (w & 3) * 32, wn = (w >> 2) * 32;
    uint32_t asb = sm_addr(As), bhb = sm_addr(Bh), blb = sm_addr(Bl);

    // A: 128 rows x 32 uint4 (row layout identical to g_xs)
#pragma unroll
    for (int t = 0; t < 16; t++) {
        int idx = tid + 256 * t;
        int row = idx >> 5, cc = idx & 31;
        *(uint4*)&As[row*264 + cc*8] =
            reinterpret_cast<const uint4*>(g_xs)[(size_t)(bm*128+row)*32 + cc];
    }
    // B: 64 rows x 16 uint4 each of hi/lo
#pragma unroll
    for (int t = 0; t < 4; t++) {
        int idx = tid + 256 * t;
        int row = idx >> 4, cc = idx & 15;
        *(uint4*)&Bh[row*136 + cc*8] =
            reinterpret_cast<const uint4*>(Wh)[(size_t)(ncol0+row)*16 + cc];
        *(uint4*)&Bl[row*136 + cc*8] =
            reinterpret_cast<const uint4*>(Wl)[(size_t)(ncol0+row)*16 + cc];
    }
    __syncthreads();

    float c[2][4][4] = {};
#pragma unroll
    for (int ki = 0; ki < 8; ki++) {
        uint32_t ah[2][4], al[2][4];
#pragma unroll
        for (int mt = 0; mt < 2; mt++) {
            ldm_x4(ah[mt], qaddr<264>(asb, wm + mt*16, ki*16, lane));
            ldm_x4(al[mt], qaddr<264>(asb, wm + mt*16, 128 + ki*16, lane));
        }
#pragma unroll
        for (int nf = 0; nf < 2; nf++) {
            uint32_t bh[4], bl[4];
            ldm_x4(bh, qaddr<136>(bhb, wn + nf*16, ki*16, lane));
            ldm_x4(bl, qaddr<136>(blb, wn + nf*16, ki*16, lane));
            uint32_t b0h[2] = {bh[0], bh[2]}, b1h[2] = {bh[1], bh[3]};
            uint32_t b0l[2] = {bl[0], bl[2]}, b1l[2] = {bl[1], bl[3]};
#pragma unroll
            for (int mt = 0; mt < 2; mt++) {
                mma_f16(c[mt][nf*2],   ah[mt], b0h);
                mma_f16(c[mt][nf*2],   al[mt], b0h);
                mma_f16(c[mt][nf*2],   ah[mt], b0l);
                mma_f16(c[mt][nf*2+1], ah[mt], b1h);
                mma_f16(c[mt][nf*2+1], al[mt], b1h);
                mma_f16(c[mt][nf*2+1], ah[mt], b1l);
            }
        }
    }
    // epilogue: split fp32 -> (hi,lo) half pairs, scatter to [s,h,r,c] layout
    __half* dst = mat ? g_ks : g_qs;
    float scale = mat ? 1.f : 0.125f;
#pragma unroll
    for (int mt = 0; mt < 2; mt++) {
#pragma unroll
        for (int rs = 0; rs < 2; rs++) {
            int m = bm*128 + wm + mt*16 + g + rs*8;
            int si = m >> 8, rr = m & 255;
#pragma unroll
            for (int ni = 0; ni < 4; ni++) {
                int col = ncol0 + wn + ni*8 + tig*2;
                int head = col >> 6, cc = col & 63;
                size_t drow = ((size_t)(si*4 + head))*256 + rr;
                float v0 = c[mt][ni][rs*2+0] * scale;
                float v1 = c[mt][ni][rs*2+1] * scale;
                __half h0 = __float2half_rn(v0), h1 = __float2half_rn(v1);
                float l0 = v0 - __half2float(h0), l1 = v1 - __half2float(h1);
                *(uint32_t*)(dst + drow*128 + cc)      = pack2(__half2float(h0), __half2float(h1));
                *(uint32_t*)(dst + drow*128 + 64 + cc) = pack2(l0, l1);
            }
        }
    }
}

// ---------------- kernel 4: single-fp16 projection GEMM (V,U) ----------------
// CTA tile 128x128, FULL K=128 resident. One sync, 8 k-steps.
#define PROJ1_SMEM (2*128*136*2)   // 69632
__global__ __launch_bounds__(256) void proj_single_kernel(const float* __restrict__ bu) {
    extern __shared__ char smem[];
    __half* As = (__half*)smem;                   // [128][136]
    __half* Bs = (__half*)(smem + 128*136*2);     // [128][136]
    int bm = blockIdx.x, bn = blockIdx.y;
    int mat = bn >> 1;                  // 0:v 1:u
    int ncol0 = (bn & 1) * 128;
    const __half* W = mat ? g_Wut : g_Wvt;
    int tid = threadIdx.x, lane = tid & 31, w = tid >> 5;
    int g = lane >> 2, tig = lane & 3;
    int wm = (w & 3) * 32, wn = (w >> 2) * 64;
    uint32_t asb = sm_addr(As), bsb = sm_addr(Bs);

#pragma unroll
    for (int t = 0; t < 8; t++) {
        int idx = tid + 256 * t;
        int row = idx >> 4, cc = idx & 15;
        *(uint4*)&As[row*136 + cc*8] =
            reinterpret_cast<const uint4*>(g_xs)[(size_t)(bm*128+row)*32 + cc];   // hi half only
        *(uint4*)&Bs[row*136 + cc*8] =
            reinterpret_cast<const uint4*>(W)[(size_t)(ncol0+row)*16 + cc];
    }
    __syncthreads();

    float c[2][8][4] = {};
#pragma unroll
    for (int ki = 0; ki < 8; ki++) {
        uint32_t a[2][4];
#pragma unroll
        for (int mt = 0; mt < 2; mt++)
            ldm_x4(a[mt], qaddr<136>(asb, wm + mt*16, ki*16, lane));
#pragma unroll
        for (int nf = 0; nf < 4; nf++) {
            uint32_t b[4];
            ldm_x4(b, qaddr<136>(bsb, wn + nf*16, ki*16, lane));
            uint32_t b0[2] = {b[0], b[2]}, b1[2] = {b[1], b[3]};
#pragma unroll
            for (int mt = 0; mt < 2; mt++) {
                mma_f16(c[mt][nf*2],   a[mt], b0);
                mma_f16(c[mt][nf*2+1], a[mt], b1);
            }
        }
    }
#pragma unroll
    for (int mt = 0; mt < 2; mt++) {
#pragma unroll
        for (int rs = 0; rs < 2; rs++) {
            int m = bm*128 + wm + mt*16 + g + rs*8;
            int si = m >> 8, rr = m & 255;
#pragma unroll
            for (int ni = 0; ni < 8; ni++) {
                int col = ncol0 + wn + ni*8 + tig*2;
                int head = col >> 6, cc = col & 63;
                size_t drow = ((size_t)(si*4 + head))*256 + rr;
                float v0 = c[mt][ni][rs*2+0], v1 = c[mt][ni][rs*2+1];
                if (mat == 0) {
                    *(uint32_t*)(g_vh + drow*64 + cc) = pack2(v0, v1);
                } else {
                    float2 b2 = *(const float2*)(bu + col);
                    float u0 = 1.f / (1.f + __expf(-(v0 + b2.x)));
                    float u1 = 1.f / (1.f + __expf(-(v1 + b2.y)));
                    *(float2*)(g_u + drow*64 + cc) = make_float2(u0, u1);
                }
            }
        }
    }
}

// ---------------- kernel 5: attention per (s, h, q-tile of 64) ----------------
// smem: Ks[64][136]h | Qs[256][136]h (Vs[256][72]h overlay) | Ph[64][264]h | Ored[64][68]f | red
#define OFF_QS 17408
#define OFF_PH 87040
#define OFF_OR 120832
#define OFF_WM 138240
#define OFF_WS 139264
#define OFF_RI 140288
#define ATTN_SMEM 140544
__global__ __launch_bounds__(512) void attn_kernel() {
    extern __shared__ char smem[];
    __half* Ks = (__half*)smem;
    __half* Qs = (__half*)(smem + OFF_QS);
    __half* Vs = (__half*)(smem + OFF_QS);
    __half* Ph = (__half*)(smem + OFF_PH);
    float* Ored = (float*)(smem + OFF_OR);
    float* wmax = (float*)(smem + OFF_WM);
    float* wsum = (float*)(smem + OFF_WS);
    float* rinv = (float*)(smem + OFF_RI);

    int b = blockIdx.x;
    int s = b >> 4, h = (b >> 2) & 3, qt = b & 3;
    int tid = threadIdx.x, lane = tid & 31, w = tid >> 5;
    int g = lane >> 2, tig = lane & 3;
    size_t base = ((size_t)(s*4 + h)) * 256;        // row base into (s,h,r) arrays

#pragma unroll
    for (int t = 0; t < 2; t++) {
        int idx = tid + 512 * t;
        int r = idx >> 4, cc = idx & 15;
        *(uint4*)&Ks[r*136 + cc*8] =
            reinterpret_cast<const uint4*>(g_ks)[(base + qt*64 + r)*16 + cc];
    }
#pragma unroll
    for (int t = 0; t < 8; t++) {
        int idx = tid + 512 * t;
        int r = idx >> 4, cc = idx & 15;
        *(uint4*)&Qs[r*136 + cc*8] =
            reinterpret_cast<const uint4*>(g_qs)[(base + r)*16 + cc];
    }
    __syncthreads();

    // ---- S = K @ Q^T (split fp16, 3-mma): warp (wq,wv) tile 16q x 64v ----
    int wq = w & 3, wv = w >> 2;
    int q0 = wq * 16, v0 = wv * 64;
    uint32_t ksb = sm_addr(Ks), qsb = sm_addr(Qs);
    float c[8][4] = {};
#pragma unroll
    for (int kt = 0; kt < 4; kt++) {
        uint32_t ah[4], al[4];
        ldm_x4(ah, qaddr<136>(ksb, q0, kt*16, lane));
        ldm_x4(al, qaddr<136>(ksb, q0, 64 + kt*16, lane));
#pragma unroll
        for (int nf = 0; nf < 4; nf++) {
            uint32_t bh[4], bl[4];
            ldm_x4(bh, qaddr<136>(qsb, v0 + nf*16, kt*16, lane));
            ldm_x4(bl, qaddr<136>(qsb, v0 + nf*16, 64 + kt*16, lane));
            uint32_t b0h[2] = {bh[0], bh[2]}, b1h[2] = {bh[1], bh[3]};
            uint32_t b0l[2] = {bl[0], bl[2]}, b1l[2] = {bl[1], bl[3]};
            mma_f16(c[nf*2],   ah, b0h);
            mma_f16(c[nf*2],   al, b0h);
            mma_f16(c[nf*2],   ah, b0l);
            mma_f16(c[nf*2+1], ah, b1h);
            mma_f16(c[nf*2+1], al, b1h);
            mma_f16(c[nf*2+1], ah, b1l);
        }
    }

    // ---- bias add + register softmax ----
    int qg0 = qt * 64;
    const float* bp = g_bias + ((size_t)h*256 + qg0 + q0) * 256;
    float m0 = -3e38f, m1 = -3e38f;
#pragma unroll
    for (int ni = 0; ni < 8; ni++) {
        int v = v0 + ni*8 + tig*2;
        float2 b0 = *(const float2*)(bp + (size_t)g*256 + v);
        float2 b1 = *(const float2*)(bp + (size_t)(g+8)*256 + v);
        c[ni][0] += b0.x; c[ni][1] += b0.y; c[ni][2] += b1.x; c[ni][3] += b1.y;
        m0 = fmaxf(m0, fmaxf(c[ni][0], c[ni][1]));
        m1 = fmaxf(m1, fmaxf(c[ni][2], c[ni][3]));
    }
    m0 = fmaxf(m0, __shfl_xor_sync(~0u, m0, 1)); m0 = fmaxf(m0, __shfl_xor_sync(~0u, m0, 2));
    m1 = fmaxf(m1, __shfl_xor_sync(~0u, m1, 1)); m1 = fmaxf(m1, __shfl_xor_sync(~0u, m1, 2));
    if (tig == 0) { wmax[wv*64 + q0 + g] = m0; wmax[wv*64 + q0 + g + 8] = m1; }
    __syncthreads();

    // load V (overlays Qs; all warps finished S mma): 256 rows x 8 uint4
#pragma unroll
    for (int t = 0; t < 4; t++) {
        int idx = tid + 512 * t;
        int r = idx >> 3, cc = idx & 7;
        *(uint4*)&Vs[r*72 + cc*8] =
            reinterpret_cast<const uint4*>(g_vh)[(base + r)*8 + cc];
    }

    float M0 = fmaxf(fmaxf(wmax[q0+g],     wmax[64+q0+g]),
                     fmaxf(wmax[128+q0+g], wmax[192+q0+g]));
    float M1 = fmaxf(fmaxf(wmax[q0+g+8],     wmax[64+q0+g+8]),
                     fmaxf(wmax[128+q0+g+8], wmax[192+q0+g+8]));
    float s0 = 0.f, s1 = 0.f;
#pragma unroll
    for (int ni = 0; ni < 8; ni++) {
        c[ni][0] = __expf(c[ni][0] - M0); c[ni][1] = __expf(c[ni][1] - M0);
        c[ni][2] = __expf(c[ni][2] - M1); c[ni][3] = __expf(c[ni][3] - M1);
        s0 += c[ni][0] + c[ni][1];
        s1 += c[ni][2] + c[ni][3];
        int v = v0 + ni*8 + tig*2;
        *(uint32_t*)&Ph[(q0+g)*264 + v]   = pack2(c[ni][0], c[ni][1]);
        *(uint32_t*)&Ph[(q0+g+8)*264 + v] = pack2(c[ni][2], c[ni][3]);
    }
    s0 += __shfl_xor_sync(~0u, s0, 1); s0 += __shfl_xor_sync(~0u, s0, 2);
    s1 += __shfl_xor_sync(~0u, s1, 1); s1 += __shfl_xor_sync(~0u, s1, 2);
    if (tig == 0) { wsum[wv*64 + q0 + g] = s0; wsum[wv*64 + q0 + g + 8] = s1; }
    __syncthreads();
    if (tid < 64)
        rinv[tid] = 1.f / (wsum[tid] + wsum[64+tid] + wsum[128+tid] + wsum[192+tid]);

    // ---- O = P @ V (single fp16): warp (wq2,wc,wv2) tile 16q x 32c, v-half 128 ----
    int wq2 = w & 3, wc = (w >> 2) & 1, wv2 = w >> 3;
    int pq0 = wq2 * 16, c0 = wc * 32, kb = wv2 * 128;
    uint32_t phb = sm_addr(Ph), vsb = sm_addr(Vs);
    float oc[4][4] = {};
#pragma unroll
    for (int kt = 0; kt < 8; kt++) {
        uint32_t a[4], bA[4], bB[4];
        ldm_x4(a, qaddr<264>(phb, pq0, kb + kt*16, lane));
        ldm_x4_t(bA, qaddr<72>(vsb, kb + kt*16, c0, lane));
        ldm_x4_t(bB, qaddr<72>(vsb, kb + kt*16, c0 + 16, lane));
        uint32_t f0[2] = {bA[0], bA[1]}, f1[2] = {bA[2], bA[3]};
        uint32_t f2[2] = {bB[0], bB[1]}, f3[2] = {bB[2], bB[3]};
        mma_f16(oc[0], a, f0); mma_f16(oc[1], a, f1);
        mma_f16(oc[2], a, f2); mma_f16(oc[3], a, f3);
    }
    if (wv2 == 1) {
#pragma unroll
        for (int j = 0; j < 4; j++) {
            int ccol = c0 + j*8 + tig*2;
            *(float2*)&Ored[(pq0+g)*68 + ccol]   = make_float2(oc[j][0], oc[j][1]);
            *(float2*)&Ored[(pq0+g+8)*68 + ccol] = make_float2(oc[j][2], oc[j][3]);
        }
    }
    __syncthreads();
    if (wv2 == 0) {
        float rv0 = rinv[pq0 + g], rv1 = rinv[pq0 + g + 8];
        int qgA = qt*64 + pq0 + g, qgB = qgA + 8;
#pragma unroll
        for (int j = 0; j < 4; j++) {
            int ccol = c0 + j*8 + tig*2;
            float2 p0 = *(float2*)&Ored[(pq0+g)*68 + ccol];
            float2 p1 = *(float2*)&Ored[(pq0+g+8)*68 + ccol];
            float2 u0 = *(const float2*)(g_u + (base + qgA)*64 + ccol);
            float2 u1 = *(const float2*)(g_u + (base + qgB)*64 + ccol);
            float oA0 = (oc[j][0] + p0.x) * rv0 * u0.x;
            float oA1 = (oc[j][1] + p0.y) * rv0 * u0.y;
            float oB0 = (oc[j][2] + p1.x) * rv1 * u1.x;
            float oB1 = (oc[j][3] + p1.y) * rv1 * u1.y;
            *(uint32_t*)(g_oh + ((size_t)(s*256 + qgA))*256 + h*64 + ccol) = pack2(oA0, oA1);
            *(uint32_t*)(g_oh + ((size_t)(s*256 + qgB))*256 + h*64 + ccol) = pack2(oB0, oB1);
        }
    }
}

// ---------------- kernel 6: output GEMM (single fp16, half A input) ----------
#define OUT_SMEM (128*136*2*2)
__global__ __launch_bounds__(256) void out_kernel(const float* __restrict__ bo,
                                                  const float* __restrict__ mask,
                                                  float* __restrict__ out) {
    extern __shared__ char smem[];
    __half* As = (__half*)smem;                  // [128][136]
    __half* Bs = (__half*)(smem + 128*136*2);    // [128][136]
    int bm = blockIdx.x;
    int tid = threadIdx.x, lane = tid & 31, w = tid >> 5;
    int g = lane >> 2, tig = lane & 3;
    int wm = (w & 3) * 32, wn = (w >> 2) * 64;
    uint32_t asb = sm_addr(As), bsb = sm_addr(Bs);
    float c[2][8][4] = {};
    for (int kt = 0; kt < 2; kt++) {
        __syncthreads();
        // A: 128 rows x 16 uint4 per K-phase; g_oh row stride = 32 uint4 (256 halves)
#pragma unroll
        for (int t = 0; t < 8; t++) {
            int idx = tid + 256 * t;
            int row = idx >> 4, cc = idx & 15;
            *(uint4*)&As[row*136 + cc*8] =
                reinterpret_cast<const uint4*>(g_oh)[(size_t)(bm*128+row)*32 + kt*16 + cc];
        }
#pragma unroll
        for (int t = 0; t < 8; t++) {
            int idx = tid + 256 * t;
            int row = idx >> 4, cc = idx & 15;
            *(uint4*)&Bs[row*136 + cc*8] =
                reinterpret_cast<const uint4*>(g_Wot)[(size_t)row*32 + kt*16 + cc];
        }
        __syncthreads();
#pragma unroll
        for (int ki = 0; ki < 8; ki++) {
            uint32_t a[2][4];
#pragma unroll
            for (int mt = 0; mt < 2; mt++)
                ldm_x4(a[mt], qaddr<136>(asb, wm + mt*16, ki*16, lane));
#pragma unroll
            for (int nf = 0; nf < 4; nf++) {
                uint32_t b[4];
                ldm_x4(b, qaddr<136>(bsb, wn + nf*16, ki*16, lane));
                uint32_t b0[2] = {b[0], b[2]}, b1[2] = {b[1], b[3]};
#pragma unroll
                for (int mt = 0; mt < 2; mt++) {
                    mma_f16(c[mt][nf*2],   a[mt], b0);
                    mma_f16(c[mt][nf*2+1], a[mt], b1);
                }
            }
        }
    }
#pragma unroll
    for (int mt = 0; mt < 2; mt++) {
#pragma unroll
        for (int rs = 0; rs < 2; rs++) {
            int m = bm*128 + wm + mt*16 + g + rs*8;
            float mk = mask[m];
#pragma unroll
            for (int ni = 0; ni < 8; ni++) {
                int col = wn + ni*8 + tig*2;
                float2 b2 = *(const float2*)(bo + col);
                float2 o2 = make_float2((c[mt][ni][rs*2+0] + b2.x) * mk,
                                        (c[mt][ni][rs*2+1] + b2.y) * mk);
                *(float2*)(out + (size_t)m * 128 + col) = o2;
            }
        }
    }
}

// ---------------- launch ----------------
extern "C" void kernel_launch(void* const* d_in, const int* in_sizes, int n_in,
                              void* d_out, int out_size) {
    const float* pair_rep = (const float*)d_in[0];
    const float* mask     = (const float*)d_in[1];
    const float* gamma    = (const float*)d_in[2];
    const float* beta     = (const float*)d_in[3];
    const float* Wq       = (const float*)d_in[4];
    const float* Wk       = (const float*)d_in[5];
    const float* Wv       = (const float*)d_in[6];
    const float* Wb       = (const float*)d_in[7];
    const float* Wu       = (const float*)d_in[8];
    const float* bu       = (const float*)d_in[9];
    const float* Wo       = (const float*)d_in[10];
    const float* bo       = (const float*)d_in[11];
    float* out = (float*)d_out;

    cudaFuncSetAttribute(attn_kernel, cudaFuncAttributeMaxDynamicSharedMemorySize, ATTN_SMEM);
    cudaFuncSetAttribute(proj_split_kernel, cudaFuncAttributeMaxDynamicSharedMemorySize, PROJS_SMEM);
    cudaFuncSetAttribute(proj_single_kernel, cudaFuncAttributeMaxDynamicSharedMemorySize, PROJ1_SMEM);
    cudaFuncSetAttribute(out_kernel, cudaFuncAttributeMaxDynamicSharedMemorySize, OUT_SMEM);

    prep_kernel<<<64, 256>>>(Wq, Wk, Wv, Wu, Wo);
    ln_kernel<<<8192, 256>>>(pair_rep, gamma, beta);
    bias_kernel<<<1024, 256>>>(Wb, mask);
    proj_split_kernel<<<dim3(512, 8), 256, PROJS_SMEM>>>();
    proj_single_kernel<<<dim3(512, 4), 256, PROJ1_SMEM>>>(bu);
    attn_kernel<<<4096, 512, ATTN_SMEM>>>();
    out_kernel<<<512, 256, OUT_SMEM>>>(bo, mask, out);
}

// round 11
// speedup vs baseline: 2.9870x; 1.1121x over previous
#include <cuda_runtime.h>
#include <cuda_fp16.h>
#include <cstdint>

#define LL 256
#define HC 256
#define NROWS (LL*LL)   // 65536

// ---------------- scratch (static device globals; no allocations) ----------
__device__ __align__(16) __half g_xs[NROWS*256];      // layernorm out split: [row][0:128 hi | 128:256 lo]
__device__ __align__(16) __half g_qs[NROWS*512];      // q split  [(s,h,r)][0:64 hi | 64:128 lo] (pre-scaled)
__device__ __align__(16) __half g_ks[NROWS*512];      // k split  same layout
__device__ __align__(16) __half g_vh[NROWS*256];      // v half   [(s,h,r)][c]
__device__ __align__(16) float  g_u [NROWS*256];      // sigmoid gate fp32 [(s,h,r)][c]
__device__ __align__(16) float  g_bias[4*NROWS];      // pair_bias + mask bias [h][q][v]
__device__ __align__(16) __half g_oh[NROWS*256];      // attention out half [s*256+q][h*64+c]
// pre-transposed / split weights [n][k] half
__device__ __align__(16) __half g_Wqt_h[256*128], g_Wqt_l[256*128];
__device__ __align__(16) __half g_Wkt_h[256*128], g_Wkt_l[256*128];
__device__ __align__(16) __half g_Wvt[256*128], g_Wut[256*128];
__device__ __align__(16) __half g_Wot[128*256];

// ---------------- mma / ldmatrix helpers ----------------
__device__ __forceinline__ uint32_t sm_addr(const void* p) {
    return (uint32_t)__cvta_generic_to_shared(p);
}
__device__ __forceinline__ void ldm_x4(uint32_t* r, uint32_t a) {
    asm volatile("ldmatrix.sync.aligned.m8n8.x4.shared.b16 {%0,%1,%2,%3}, [%4];"
                 : "=r"(r[0]), "=r"(r[1]), "=r"(r[2]), "=r"(r[3]) : "r"(a));
}
__device__ __forceinline__ void ldm_x4_t(uint32_t* r, uint32_t a) {
    asm volatile("ldmatrix.sync.aligned.m8n8.x4.trans.shared.b16 {%0,%1,%2,%3}, [%4];"
                 : "=r"(r[0]), "=r"(r[1]), "=r"(r[2]), "=r"(r[3]) : "r"(a));
}
__device__ __forceinline__ void mma_f16(float* c, const uint32_t* a, const uint32_t* b) {
    asm volatile("mma.sync.aligned.m16n8k16.row.col.f32.f16.f16.f32 "
                 "{%0,%1,%2,%3},{%4,%5,%6,%7},{%8,%9},{%0,%1,%2,%3};"
                 : "+f"(c[0]), "+f"(c[1]), "+f"(c[2]), "+f"(c[3])
                 : "r"(a[0]), "r"(a[1]), "r"(a[2]), "r"(a[3]), "r"(b[0]), "r"(b[1]));
}
template<int STRIDE>
__device__ __forceinline__ uint32_t qaddr(uint32_t base, int r0, int c0, int lane) {
    int t = lane >> 3, tr = lane & 7;
    return base + (uint32_t)(((r0 + tr + (t & 1) * 8) * STRIDE + c0 + (t >> 1) * 8) * 2);
}
__device__ __forceinline__ uint32_t pack2(float x, float y) {
    __half2 h = __floats2half2_rn(x, y);
    return *(uint32_t*)&h;
}

// ---------------- kernel 0: weight transpose + split ----------------
__global__ void prep_kernel(const float* __restrict__ Wq, const float* __restrict__ Wk,
                            const float* __restrict__ Wv, const float* __restrict__ Wu,
                            const float* __restrict__ Wo) {
    for (int idx = blockIdx.x * 256 + threadIdx.x; idx < 32768; idx += gridDim.x * 256) {
        int k = idx >> 8, n = idx & 255;
        float xq = Wq[idx]; __half hq = __float2half_rn(xq);
        g_Wqt_h[n*128+k] = hq; g_Wqt_l[n*128+k] = __float2half_rn(xq - __half2float(hq));
        float xk = Wk[idx]; __half hk = __float2half_rn(xk);
        g_Wkt_h[n*128+k] = hk; g_Wkt_l[n*128+k] = __float2half_rn(xk - __half2float(hk));
        g_Wvt[n*128+k] = __float2half_rn(Wv[idx]);
        g_Wut[n*128+k] = __float2half_rn(Wu[idx]);
        int k2 = idx >> 7, n2 = idx & 127;
        g_Wot[n2*256+k2] = __float2half_rn(Wo[idx]);
    }
}

// ---------------- kernel 1: layernorm (split-half out only) ----------------
__global__ __launch_bounds__(256) void ln_kernel(const float* __restrict__ in,
                                                 const float* __restrict__ gamma,
                                                 const float* __restrict__ beta) {
    int row  = blockIdx.x * 8 + (threadIdx.x >> 5);
    int lane = threadIdx.x & 31;
    float4 v = reinterpret_cast<const float4*>(in)[(size_t)row * 32 + lane];
    float s  = v.x + v.y + v.z + v.w;
    float ss = v.x*v.x + v.y*v.y + v.z*v.z + v.w*v.w;
#pragma unroll
    for (int o = 16; o; o >>= 1) {
        s  += __shfl_xor_sync(0xffffffffu, s,  o);
        ss += __shfl_xor_sync(0xffffffffu, ss, o);
    }
    float mu  = s * (1.f / 128.f);
    float var = fmaxf(ss * (1.f / 128.f) - mu * mu, 0.f);
    float inv = rsqrtf(var + 1e-5f);
    float4 g = reinterpret_cast<const float4*>(gamma)[lane];
    float4 b = reinterpret_cast<const float4*>(beta)[lane];
    float o4[4];
    o4[0] = (v.x - mu) * inv * g.x + b.x;
    o4[1] = (v.y - mu) * inv * g.y + b.y;
    o4[2] = (v.z - mu) * inv * g.z + b.z;
    o4[3] = (v.w - mu) * inv * g.w + b.w;
    __half h[4]; float l[4];
#pragma unroll
    for (int i = 0; i < 4; i++) { h[i] = __float2half_rn(o4[i]); l[i] = o4[i] - __half2float(h[i]); }
    uint2 hi2 = make_uint2(pack2(__half2float(h[0]), __half2float(h[1])),
                           pack2(__half2float(h[2]), __half2float(h[3])));
    uint2 lo2 = make_uint2(pack2(l[0], l[1]), pack2(l[2], l[3]));
    uint2* dst = (uint2*)(g_xs + (size_t)row * 256);
    dst[lane] = hi2;
    dst[32 + lane] = lo2;
}

// ---------------- kernel 2: pair_bias + mask bias ----------------
__global__ __launch_bounds__(256) void bias_kernel(const float* __restrict__ Wb,
                                                   const float* __restrict__ mask) {
    __shared__ float Xs[64][132];
    __shared__ float Wbs[4][132];
    int p0 = blockIdx.x * 64;
    int tid = threadIdx.x;
#pragma unroll
    for (int t = 0; t < 2; t++) {
        int idx = tid + 256 * t;
        Wbs[idx & 3][idx >> 2] = Wb[idx];
    }
#pragma unroll
    for (int i = 0; i < 4; i++) {
        int idx = tid + 256 * i;
        int row = idx >> 4, j = idx & 15;
        const uint4* rb = reinterpret_cast<const uint4*>(g_xs + (size_t)(p0+row)*256);
        uint4 hv = rb[j], lv = rb[16 + j];
        const __half2* hp = (const __half2*)&hv;
        const __half2* lp = (const __half2*)&lv;
        float out8[8];
#pragma unroll
        for (int e = 0; e < 4; e++) {
            float2 hf = __half22float2(hp[e]);
            float2 lf = __half22float2(lp[e]);
            out8[e*2+0] = hf.x + lf.x;
            out8[e*2+1] = hf.y + lf.y;
        }
        *(float4*)&Xs[row][j*8]     = make_float4(out8[0], out8[1], out8[2], out8[3]);
        *(float4*)&Xs[row][j*8 + 4] = make_float4(out8[4], out8[5], out8[6], out8[7]);
    }
    __syncthreads();
    int p = tid >> 2, hh = tid & 3;
    float acc = 0.f;
#pragma unroll
    for (int i = 0; i < 32; i++) {
        float4 xv = *(float4*)&Xs[p][i*4];
        float4 wv = *(float4*)&Wbs[hh][i*4];
        acc += xv.x*wv.x + xv.y*wv.y + xv.z*wv.z + xv.w*wv.w;
    }
    int pair = p0 + p;
    g_bias[(size_t)hh * 65536 + pair] = acc + 1e9f * (mask[pair] - 1.f);
}

// ---------------- kernel 3: split projection GEMM (Q,K) ----------------
// CTA tile 64m x 64n, FULL K=128 resident (hi|lo). 68.6KB smem -> 3 CTAs/SM.
#define PROJS_SMEM (64*264*2 + 2*64*136*2)   // 33792 + 34816 = 68608
__global__ __launch_bounds__(256, 3) void proj_split_kernel() {
    extern __shared__ char smem[];
    __half* As = (__half*)smem;                       // [64][264]: cols 0..127 hi k, 128..255 lo k
    __half* Bh = (__half*)(smem + 64*264*2);          // [64][136]
    __half* Bl = (__half*)(smem + 64*264*2 + 64*136*2);
    int bm = blockIdx.x, bn = blockIdx.y;             // bm 0..1023, bn 0..7
    int mat = bn >> 2;                                // 0:q 1:k
    int ncol0 = (bn & 3) * 64;
    const __half* Wh = mat ? g_Wkt_h : g_Wqt_h;
    const __half* Wl = mat ? g_Wkt_l : g_Wqt_l;
    int tid = threadIdx.x, lane = tid & 31, w = tid >> 5;
    int g = lane >> 2, tig = lane & 3;
    int wm = (w & 3) * 16, wn = (w >> 2) * 32;
    uint32_t asb = sm_addr(As), bhb = sm_addr(Bh), blb = sm_addr(Bl);

    // A: 64 rows x 32 uint4 (row layout identical to g_xs)
#pragma unroll
    for (int t = 0; t < 8; t++) {
        int idx = tid + 256 * t;
        int row = idx >> 5, cc = idx & 31;
        *(uint4*)&As[row*264 + cc*8] =
            reinterpret_cast<const uint4*>(g_xs)[(size_t)(bm*64+row)*32 + cc];
    }
    // B: 64 rows x 16 uint4 each of hi/lo
#pragma unroll
    for (int t = 0; t < 4; t++) {
        int idx = tid + 256 * t;
        int row = idx >> 4, cc = idx & 15;
        *(uint4*)&Bh[row*136 + cc*8] =
            reinterpret_cast<const uint4*>(Wh)[(size_t)(ncol0+row)*16 + cc];
        *(uint4*)&Bl[row*136 + cc*8] =
            reinterpret_cast<const uint4*>(Wl)[(size_t)(ncol0+row)*16 + cc];
    }
    __syncthreads();

    float c[4][4] = {};
#pragma unroll
    for (int ki = 0; ki < 8; ki++) {
        uint32_t ah[4], al[4];
        ldm_x4(ah, qaddr<264>(asb, wm, ki*16, lane));
        ldm_x4(al, qaddr<264>(asb, wm, 128 + ki*16, lane));
#pragma unroll
        for (int nf = 0; nf < 2; nf++) {
            uint32_t bh[4], bl[4];
            ldm_x4(bh, qaddr<136>(bhb, wn + nf*16, ki*16, lane));
            ldm_x4(bl, qaddr<136>(blb, wn + nf*16, ki*16, lane));
            uint32_t b0h[2] = {bh[0], bh[2]}, b1h[2] = {bh[1], bh[3]};
            uint32_t b0l[2] = {bl[0], bl[2]}, b1l[2] = {bl[1], bl[3]};
            mma_f16(c[nf*2],   ah, b0h);
            mma_f16(c[nf*2],   al, b0h);
            mma_f16(c[nf*2],   ah, b0l);
            mma_f16(c[nf*2+1], ah, b1h);
            mma_f16(c[nf*2+1], al, b1h);
            mma_f16(c[nf*2+1], ah, b1l);
        }
    }
    // epilogue: split fp32 -> (hi,lo) half pairs, scatter to [s,h,r,c] layout
    __half* dst = mat ? g_ks : g_qs;
    float scale = mat ? 1.f : 0.125f;
#pragma unroll
    for (int rs = 0; rs < 2; rs++) {
        int m = bm*64 + wm + g + rs*8;
        int si = m >> 8, rr = m & 255;
#pragma unroll
        for (int ni = 0; ni < 4; ni++) {
            int col = ncol0 + wn + ni*8 + tig*2;
            int head = col >> 6, cc = col & 63;
            size_t drow = ((size_t)(si*4 + head))*256 + rr;
            float v0 = c[ni][rs*2+0] * scale;
            float v1 = c[ni][rs*2+1] * scale;
            __half h0 = __float2half_rn(v0), h1 = __float2half_rn(v1);
            float l0 = v0 - __half2float(h0), l1 = v1 - __half2float(h1);
            *(uint32_t*)(dst + drow*128 + cc)      = pack2(__half2float(h0), __half2float(h1));
            *(uint32_t*)(dst + drow*128 + 64 + cc) = pack2(l0, l1);
        }
    }
}

// ---------------- kernel 4: single-fp16 projection GEMM (V,U) ----------------
// CTA tile 128x128, FULL K=128 resident. One sync, 8 k-steps.
#define PROJ1_SMEM (2*128*136*2)   // 69632
__global__ __launch_bounds__(256) void proj_single_kernel(const float* __restrict__ bu) {
    extern __shared__ char smem[];
    __half* As = (__half*)smem;                   // [128][136]
    __half* Bs = (__half*)(smem + 128*136*2);     // [128][136]
    int bm = blockIdx.x, bn = blockIdx.y;
    int mat = bn >> 1;                  // 0:v 1:u
    int ncol0 = (bn & 1) * 128;
    const __half* W = mat ? g_Wut : g_Wvt;
    int tid = threadIdx.x, lane = tid & 31, w = tid >> 5;
    int g = lane >> 2, tig = lane & 3;
    int wm = (w & 3) * 32, wn = (w >> 2) * 64;
    uint32_t asb = sm_addr(As), bsb = sm_addr(Bs);

#pragma unroll
    for (int t = 0; t < 8; t++) {
        int idx = tid + 256 * t;
        int row = idx >> 4, cc = idx & 15;
        *(uint4*)&As[row*136 + cc*8] =
            reinterpret_cast<const uint4*>(g_xs)[(size_t)(bm*128+row)*32 + cc];   // hi half only
        *(uint4*)&Bs[row*136 + cc*8] =
            reinterpret_cast<const uint4*>(W)[(size_t)(ncol0+row)*16 + cc];
    }
    __syncthreads();

    float c[2][8][4] = {};
#pragma unroll
    for (int ki = 0; ki < 8; ki++) {
        uint32_t a[2][4];
#pragma unroll
        for (int mt = 0; mt < 2; mt++)
            ldm_x4(a[mt], qaddr<136>(asb, wm + mt*16, ki*16, lane));
#pragma unroll
        for (int nf = 0; nf < 4; nf++) {
            uint32_t b[4];
            ldm_x4(b, qaddr<136>(bsb, wn + nf*16, ki*16, lane));
            uint32_t b0[2] = {b[0], b[2]}, b1[2] = {b[1], b[3]};
#pragma unroll
            for (int mt = 0; mt < 2; mt++) {
                mma_f16(c[mt][nf*2],   a[mt], b0);
                mma_f16(c[mt][nf*2+1], a[mt], b1);
            }
        }
    }
#pragma unroll
    for (int mt = 0; mt < 2; mt++) {
#pragma unroll
        for (int rs = 0; rs < 2; rs++) {
            int m = bm*128 + wm + mt*16 + g + rs*8;
            int si = m >> 8, rr = m & 255;
#pragma unroll
            for (int ni = 0; ni < 8; ni++) {
                int col = ncol0 + wn + ni*8 + tig*2;
                int head = col >> 6, cc = col & 63;
                size_t drow = ((size_t)(si*4 + head))*256 + rr;
                float v0 = c[mt][ni][rs*2+0], v1 = c[mt][ni][rs*2+1];
                if (mat == 0) {
                    *(uint32_t*)(g_vh + drow*64 + cc) = pack2(v0, v1);
                } else {
                    float2 b2 = *(const float2*)(bu + col);
                    float u0 = 1.f / (1.f + __expf(-(v0 + b2.x)));
                    float u1 = 1.f / (1.f + __expf(-(v1 + b2.y)));
                    *(float2*)(g_u + drow*64 + cc) = make_float2(u0, u1);
                }
            }
        }
    }
}

// ---------------- kernel 5: attention per (s, h, q-tile of 64) ----------------
// smem 91.4KB -> 2 CTAs/SM.
//   Ks [64][136]h at 0          (17408B)
//   Qbuf [128][136]h at 17408   (34816B) -- Q loaded in 2 phases; Ph overlays after S
//   Ph [64][264]h at 17408      (33792B)
//   Vs [256][72]h at 52224      (36864B)
//   wmax/wsum/rinv at 89088
#define AT_QB 17408
#define AT_PH 17408
#define AT_VS 52224
#define AT_WM 89088
#define AT_WS 90112
#define AT_RI 91136
#define ATTN_SMEM 91392
__global__ __launch_bounds__(512, 2) void attn_kernel() {
    extern __shared__ char smem[];
    __half* Ks = (__half*)smem;
    __half* Qb = (__half*)(smem + AT_QB);
    __half* Ph = (__half*)(smem + AT_PH);
    __half* Vs = (__half*)(smem + AT_VS);
    float* wmax = (float*)(smem + AT_WM);
    float* wsum = (float*)(smem + AT_WS);
    float* rinv = (float*)(smem + AT_RI);

    int b = blockIdx.x;
    int s = b >> 4, h = (b >> 2) & 3, qt = b & 3;
    int tid = threadIdx.x, lane = tid & 31, w = tid >> 5;
    int g = lane >> 2, tig = lane & 3;
    size_t base = ((size_t)(s*4 + h)) * 256;        // row base into (s,h,r) arrays

    // K tile: 64 rows x 16 uint4
#pragma unroll
    for (int t = 0; t < 2; t++) {
        int idx = tid + 512 * t;
        int r = idx >> 4, cc = idx & 15;
        *(uint4*)&Ks[r*136 + cc*8] =
            reinterpret_cast<const uint4*>(g_ks)[(base + qt*64 + r)*16 + cc];
    }

    // ---- S = K @ Q^T (split fp16, 3-mma) in 2 Q-phases of 128 v-rows ----
    // warp (wq,wv): 16q x 32v per phase; global v = p*128 + wv*32 + nn*8 + tig*2
    int wq = w & 3, wv = w >> 2;
    int q0 = wq * 16;
    uint32_t ksb = sm_addr(Ks), qbb = sm_addr(Qb);
    float c[8][4] = {};
#pragma unroll
    for (int p = 0; p < 2; p++) {
        if (p) __syncthreads();     // protect Qb overwrite
        // Q phase load: 128 rows x 16 uint4
#pragma unroll
        for (int t = 0; t < 4; t++) {
            int idx = tid + 512 * t;
            int r = idx >> 4, cc = idx & 15;
            *(uint4*)&Qb[r*136 + cc*8] =
                reinterpret_cast<const uint4*>(g_qs)[(base + p*128 + r)*16 + cc];
        }
        __syncthreads();
#pragma unroll
        for (int kt = 0; kt < 4; kt++) {
            uint32_t ah[4], al[4];
            ldm_x4(ah, qaddr<136>(ksb, q0, kt*16, lane));
            ldm_x4(al, qaddr<136>(ksb, q0, 64 + kt*16, lane));
#pragma unroll
            for (int nf = 0; nf < 2; nf++) {
                uint32_t bh[4], bl[4];
                ldm_x4(bh, qaddr<136>(qbb, wv*32 + nf*16, kt*16, lane));
                ldm_x4(bl, qaddr<136>(qbb, wv*32 + nf*16, 64 + kt*16, lane));
                uint32_t b0h[2] = {bh[0], bh[2]}, b1h[2] = {bh[1], bh[3]};
                uint32_t b0l[2] = {bl[0], bl[2]}, b1l[2] = {bl[1], bl[3]};
                mma_f16(c[p*4 + nf*2],   ah, b0h);
                mma_f16(c[p*4 + nf*2],   al, b0h);
                mma_f16(c[p*4 + nf*2],   ah, b0l);
                mma_f16(c[p*4 + nf*2+1], ah, b1h);
                mma_f16(c[p*4 + nf*2+1], al, b1h);
                mma_f16(c[p*4 + nf*2+1], ah, b1l);
            }
        }
    }

    // ---- bias add + register max ----
    const float* bp = g_bias + ((size_t)h*256 + qt*64 + q0) * 256;
    float m0 = -3e38f, m1 = -3e38f;
#pragma unroll
    for (int ni = 0; ni < 8; ni++) {
        int v = (ni >> 2)*128 + wv*32 + (ni & 3)*8 + tig*2;
        float2 b0 = *(const float2*)(bp + (size_t)g*256 + v);
        float2 b1 = *(const float2*)(bp + (size_t)(g+8)*256 + v);
        c[ni][0] += b0.x; c[ni][1] += b0.y; c[ni][2] += b1.x; c[ni][3] += b1.y;
        m0 = fmaxf(m0, fmaxf(c[ni][0], c[ni][1]));
        m1 = fmaxf(m1, fmaxf(c[ni][2], c[ni][3]));
    }
    m0 = fmaxf(m0, __shfl_xor_sync(~0u, m0, 1)); m0 = fmaxf(m0, __shfl_xor_sync(~0u, m0, 2));
    m1 = fmaxf(m1, __shfl_xor_sync(~0u, m1, 1)); m1 = fmaxf(m1, __shfl_xor_sync(~0u, m1, 2));
    if (tig == 0) { wmax[wv*64 + q0 + g] = m0; wmax[wv*64 + q0 + g + 8] = m1; }
    __syncthreads();    // all S-mma Qb reads done; Ph (overlaying Qb) may now be written

    // load full V (own region): 256 rows x 8 uint4
#pragma unroll
    for (int t = 0; t < 4; t++) {
        int idx = tid + 512 * t;
        int r = idx >> 3, cc = idx & 7;
        *(uint4*)&Vs[r*72 + cc*8] =
            reinterpret_cast<const uint4*>(g_vh)[(base + r)*8 + cc];
    }

    float M0 = fmaxf(fmaxf(wmax[q0+g],     wmax[64+q0+g]),
                     fmaxf(wmax[128+q0+g], wmax[192+q0+g]));
    float M1 = fmaxf(fmaxf(wmax[q0+g+8],     wmax[64+q0+g+8]),
                     fmaxf(wmax[128+q0+g+8], wmax[192+q0+g+8]));
    float s0 = 0.f, s1 = 0.f;
#pragma unroll
    for (int ni = 0; ni < 8; ni++) {
        c[ni][0] = __expf(c[ni][0] - M0); c[ni][1] = __expf(c[ni][1] - M0);
        c[ni][2] = __expf(c[ni][2] - M1); c[ni][3] = __expf(c[ni][3] - M1);
        s0 += c[ni][0] + c[ni][1];
        s1 += c[ni][2] + c[ni][3];
        int v = (ni >> 2)*128 + wv*32 + (ni & 3)*8 + tig*2;
        *(uint32_t*)&Ph[(q0+g)*264 + v]   = pack2(c[ni][0], c[ni][1]);
        *(uint32_t*)&Ph[(q0+g+8)*264 + v] = pack2(c[ni][2], c[ni][3]);
    }
    s0 += __shfl_xor_sync(~0u, s0, 1); s0 += __shfl_xor_sync(~0u, s0, 2);
    s1 += __shfl_xor_sync(~0u, s1, 1); s1 += __shfl_xor_sync(~0u, s1, 2);
    if (tig == 0) { wsum[wv*64 + q0 + g] = s0; wsum[wv*64 + q0 + g + 8] = s1; }
    __syncthreads();    // Ph + Vs + wsum complete
    if (tid < 64)
        rinv[tid] = 1.f / (wsum[tid] + wsum[64+tid] + wsum[128+tid] + wsum[192+tid]);
    __syncthreads();    // rinv visible

    // ---- O = P @ V (single fp16): warp tile 16q x 16c, FULL k=256 ----
    int wq2 = w & 3, wc = w >> 2;
    int pq0 = wq2 * 16, c0 = wc * 16;
    uint32_t phb = sm_addr(Ph), vsb = sm_addr(Vs);
    float oc[2][4] = {};
#pragma unroll
    for (int kt = 0; kt < 16; kt++) {
        uint32_t a[4], bt[4];
        ldm_x4(a, qaddr<264>(phb, pq0, kt*16, lane));
        ldm_x4_t(bt, qaddr<72>(vsb, kt*16, c0, lane));
        uint32_t f0[2] = {bt[0], bt[1]}, f1[2] = {bt[2], bt[3]};
        mma_f16(oc[0], a, f0);
        mma_f16(oc[1], a, f1);
    }
    // epilogue: /rowsum, * sigmoid gate, store half
    {
        float rv0 = rinv[pq0 + g], rv1 = rinv[pq0 + g + 8];
        int qgA = qt*64 + pq0 + g, qgB = qgA + 8;
#pragma unroll
        for (int j = 0; j < 2; j++) {
            int ccol = c0 + j*8 + tig*2;
            float2 u0 = *(const float2*)(g_u + (base + qgA)*64 + ccol);
            float2 u1 = *(const float2*)(g_u + (base + qgB)*64 + ccol);
            float oA0 = oc[j][0] * rv0 * u0.x;
            float oA1 = oc[j][1] * rv0 * u0.y;
            float oB0 = oc[j][2] * rv1 * u1.x;
            float oB1 = oc[j][3] * rv1 * u1.y;
            *(uint32_t*)(g_oh + ((size_t)(s*256 + qgA))*256 + h*64 + ccol) = pack2(oA0, oA1);
            *(uint32_t*)(g_oh + ((size_t)(s*256 + qgB))*256 + h*64 + ccol) = pack2(oB0, oB1);
        }
    }
}

// ---------------- kernel 6: output GEMM (single fp16, half A input) ----------
#define OUT_SMEM (128*136*2*2)
__global__ __launch_bounds__(256) void out_kernel(const float* __restrict__ bo,
                                                  const float* __restrict__ mask,
                                                  float* __restrict__ out) {
    extern __shared__ char smem[];
    __half* As = (__half*)smem;                  // [128][136]
    __half* Bs = (__half*)(smem + 128*136*2);    // [128][136]
    int bm = blockIdx.x;
    int tid = threadIdx.x, lane = tid & 31, w = tid >> 5;
    int g = lane >> 2, tig = lane & 3;
    int wm = (w & 3) * 32, wn = (w >> 2) * 64;
    uint32_t asb = sm_addr(As), bsb = sm_addr(Bs);
    float c[2][8][4] = {};
    for (int kt = 0; kt < 2; kt++) {
        __syncthreads();
        // A: 128 rows x 16 uint4 per K-phase; g_oh row stride = 32 uint4 (256 halves)
#pragma unroll
        for (int t = 0; t < 8; t++) {
            int idx = tid + 256 * t;
            int row = idx >> 4, cc = idx & 15;
            *(uint4*)&As[row*136 + cc*8] =
                reinterpret_cast<const uint4*>(g_oh)[(size_t)(bm*128+row)*32 + kt*16 + cc];
        }
#pragma unroll
        for (int t = 0; t < 8; t++) {
            int idx = tid + 256 * t;
            int row = idx >> 4, cc = idx & 15;
            *(uint4*)&Bs[row*136 + cc*8] =
                reinterpret_cast<const uint4*>(g_Wot)[(size_t)row*32 + kt*16 + cc];
        }
        __syncthreads();
#pragma unroll
        for (int ki = 0; ki < 8; ki++) {
            uint32_t a[2][4];
#pragma unroll
            for (int mt = 0; mt < 2; mt++)
                ldm_x4(a[mt], qaddr<136>(asb, wm + mt*16, ki*16, lane));
#pragma unroll
            for (int nf = 0; nf < 4; nf++) {
                uint32_t b[4];
                ldm_x4(b, qaddr<136>(bsb, wn + nf*16, ki*16, lane));
                uint32_t b0[2] = {b[0], b[2]}, b1[2] = {b[1], b[3]};
#pragma unroll
                for (int mt = 0; mt < 2; mt++) {
                    mma_f16(c[mt][nf*2],   a[mt], b0);
                    mma_f16(c[mt][nf*2+1], a[mt], b1);
                }
            }
        }
    }
#pragma unroll
    for (int mt = 0; mt < 2; mt++) {
#pragma unroll
        for (int rs = 0; rs < 2; rs++) {
            int m = bm*128 + wm + mt*16 + g + rs*8;
            float mk = mask[m];
#pragma unroll
            for (int ni = 0; ni < 8; ni++) {
                int col = wn + ni*8 + tig*2;
                float2 b2 = *(const float2*)(bo + col);
                float2 o2 = make_float2((c[mt][ni][rs*2+0] + b2.x) * mk,
                                        (c[mt][ni][rs*2+1] + b2.y) * mk);
                *(float2*)(out + (size_t)m * 128 + col) = o2;
            }
        }
    }
}

// ---------------- launch ----------------
extern "C" void kernel_launch(void* const* d_in, const int* in_sizes, int n_in,
                              void* d_out, int out_size) {
    const float* pair_rep = (const float*)d_in[0];
    const float* mask     = (const float*)d_in[1];
    const float* gamma    = (const float*)d_in[2];
    const float* beta     = (const float*)d_in[3];
    const float* Wq       = (const float*)d_in[4];
    const float* Wk       = (const float*)d_in[5];
    const float* Wv       = (const float*)d_in[6];
    const float* Wb       = (const float*)d_in[7];
    const float* Wu       = (const float*)d_in[8];
    const float* bu       = (const float*)d_in[9];
    const float* Wo       = (const float*)d_in[10];
    const float* bo       = (const float*)d_in[11];
    float* out = (float*)d_out;

    cudaFuncSetAttribute(attn_kernel, cudaFuncAttributeMaxDynamicSharedMemorySize, ATTN_SMEM);
    cudaFuncSetAttribute(proj_split_kernel, cudaFuncAttributeMaxDynamicSharedMemorySize, PROJS_SMEM);
    cudaFuncSetAttribute(proj_single_kernel, cudaFuncAttributeMaxDynamicSharedMemorySize, PROJ1_SMEM);
    cudaFuncSetAttribute(out_kernel, cudaFuncAttributeMaxDynamicSharedMemorySize, OUT_SMEM);

    prep_kernel<<<64, 256>>>(Wq, Wk, Wv, Wu, Wo);
    ln_kernel<<<8192, 256>>>(pair_rep, gamma, beta);
    bias_kernel<<<1024, 256>>>(Wb, mask);
    proj_split_kernel<<<dim3(1024, 8), 256, PROJS_SMEM>>>();
    proj_single_kernel<<<dim3(512, 4), 256, PROJ1_SMEM>>>(bu);
    attn_kernel<<<4096, 512, ATTN_SMEM>>>();
    out_kernel<<<512, 256, OUT_SMEM>>>(bo, mask, out);
}